// round 10
// baseline (speedup 1.0000x reference)
#include <cuda_runtime.h>
#include <cuda_fp16.h>
#include <cstdint>
#include <cstddef>

#define EMBED    1024
#define NHEADS   16
#define HDIM     64
#define WSIZE    256
#define NWIN     64
#define MTOT     (NWIN*WSIZE)     /* 16384 */
#define LTOT     (MTOT-1)         /* 16383 */
#define QKVN     (3*EMBED)        /* 3072  */

// Scratch (allocation-free rule: __device__ globals)
__device__ __half g_xh[(size_t)MTOT * EMBED];    // x fp16, padding row zeroed
__device__ __half g_wqkv[(size_t)QKVN * EMBED];  // qkv_w fp16
__device__ __half g_wproj[(size_t)EMBED * EMBED];// proj_w fp16
__device__ __half g_qkvh[(size_t)MTOT * QKVN];   // gathered-order qkv fp16
__device__ __half g_osch[(size_t)MTOT * EMBED];  // scattered attention out fp16

__device__ __forceinline__ float ex2f(float x) {
    float y;
    asm("ex2.approx.f32 %0, %1;" : "=f"(y) : "f"(x));
    return y;
}
__device__ __forceinline__ uint32_t packh2(float lo, float hi) {
    __half2 h = __floats2half2_rn(lo, hi);
    return *reinterpret_cast<uint32_t*>(&h);
}
__device__ __forceinline__ void mma_f16(float* c, const uint32_t* a, const uint32_t* b) {
    asm volatile(
        "mma.sync.aligned.m16n8k16.row.col.f32.f16.f16.f32 "
        "{%0,%1,%2,%3}, {%4,%5,%6,%7}, {%8,%9}, {%0,%1,%2,%3};"
        : "+f"(c[0]), "+f"(c[1]), "+f"(c[2]), "+f"(c[3])
        : "r"(a[0]), "r"(a[1]), "r"(a[2]), "r"(a[3]), "r"(b[0]), "r"(b[1]));
}
__device__ __forceinline__ void ldsm_x4(uint32_t* r, uint32_t addr) {
    asm volatile("ldmatrix.sync.aligned.m8n8.x4.shared.b16 {%0,%1,%2,%3}, [%4];"
                 : "=r"(r[0]), "=r"(r[1]), "=r"(r[2]), "=r"(r[3]) : "r"(addr));
}
__device__ __forceinline__ void ldsm_x4_t(uint32_t* r, uint32_t addr) {
    asm volatile("ldmatrix.sync.aligned.m8n8.x4.trans.shared.b16 {%0,%1,%2,%3}, [%4];"
                 : "=r"(r[0]), "=r"(r[1]), "=r"(r[2]), "=r"(r[3]) : "r"(addr));
}
__device__ __forceinline__ uint32_t smem_u32(const void* p) {
    uint32_t a;
    asm("{ .reg .u64 t; cvta.to.shared.u64 t, %1; cvt.u32.u64 %0, t; }"
        : "=r"(a) : "l"(p));
    return a;
}
__device__ __forceinline__ void cp16(uint32_t smem, const void* g) {
    asm volatile("cp.async.cg.shared.global [%0], [%1], 16;" :: "r"(smem), "l"(g));
}
__device__ __forceinline__ void cp_commit() {
    asm volatile("cp.async.commit_group;" ::: "memory");
}
__device__ __forceinline__ void cp_wait0() {
    asm volatile("cp.async.wait_group 0;" ::: "memory");
}

// ---------------------------------------------------------------------------
// fp32 -> fp16 conversion, zero-fills [n_src, n_tot)
// ---------------------------------------------------------------------------
__global__ void cvt_kernel(const float* __restrict__ src, __half* __restrict__ dst,
                           int n_src, int n_tot)
{
    int i = (blockIdx.x * blockDim.x + threadIdx.x) << 2;
    if (i >= n_tot) return;
    uint2 u;
    if (i < n_src) {
        float4 v = *reinterpret_cast<const float4*>(src + i);
        u.x = packh2(v.x, v.y);
        u.y = packh2(v.z, v.w);
    } else {
        u = make_uint2(0u, 0u);
    }
    *reinterpret_cast<uint2*>(dst + i) = u;
}

// ---------------------------------------------------------------------------
// fp16 tensor-core GEMM (fp32 accum), cp.async pipeline:
//   C[m][n] = sum_k A[row(m)][k] * B[n][k] + bias[n]
//   BM=128, BN=256, BK=32 halves. 256 threads, 8 warps (2x4), warp tile 64x64.
// ---------------------------------------------------------------------------
#define GSTR    40                    /* halves per smem row   */
#define A_TILE_H (128 * GSTR)         /* 5120 halves, 10240 B  */
#define B_TILE_H (256 * GSTR)         /* 10240 halves, 20480 B */
#define GEMM_SMEM_B ((2 * (A_TILE_H + B_TILE_H)) * 2)   /* 61440 B */

__global__ void __launch_bounds__(256)
h16_gemm_kernel(const __half* __restrict__ A,
                const __half* __restrict__ B,
                const float* __restrict__ bias,
                float* __restrict__ Cf,
                __half* __restrict__ Ch,
                const int* __restrict__ gidx,
                int Mrows, int N, int K)
{
    extern __shared__ __half smh[];
    // layout: As[2][128][40], Bs[2][256][40]
    __shared__ int arow[128];

    const int tid  = threadIdx.x;
    const int lane = tid & 31;
    const int wid  = tid >> 5;
    const int wm   = wid & 1;        // 2 warp rows (64 each)
    const int wn   = wid >> 1;       // 4 warp cols (64 each)
    const int bm   = blockIdx.y * 128;
    const int bn   = blockIdx.x * 256;

    if (tid < 128) {
        int m = bm + tid;
        arow[tid] = (m < Mrows) ? (gidx ? gidx[m] : m) : 0;
    }
    __syncthreads();

    const uint32_t smb   = smem_u32(smh);
    const uint32_t bsOff = 2 * A_TILE_H * 2;          // byte offset of Bs
    const uint32_t ABUF  = A_TILE_H * 2;              // bytes per A buffer
    const uint32_t BBUF  = B_TILE_H * 2;              // bytes per B buffer

    // cp.async copy mapping: 16B chunks; chunk c -> row=c>>2, col=(c&3)*8 halves
    auto copy_tile = [&](int buf, int k0) {
        #pragma unroll
        for (int i = 0; i < 2; i++) {               // A: 512 chunks
            int c = tid + i * 256;
            int row = c >> 2, col = (c & 3) << 3;
            uint32_t dst = smb + buf * ABUF + ((row * GSTR + col) << 1);
            cp16(dst, &A[(size_t)arow[row] * K + k0 + col]);
        }
        #pragma unroll
        for (int i = 0; i < 4; i++) {               // B: 1024 chunks
            int c = tid + i * 256;
            int row = c >> 2, col = (c & 3) << 3;
            uint32_t dst = smb + bsOff + buf * BBUF + ((row * GSTR + col) << 1);
            cp16(dst, &B[(size_t)(bn + row) * K + k0 + col]);
        }
        cp_commit();
    };

    float acc[4][8][4];
    #pragma unroll
    for (int mt = 0; mt < 4; mt++)
        #pragma unroll
        for (int nt = 0; nt < 8; nt++)
            #pragma unroll
            for (int i = 0; i < 4; i++) acc[mt][nt][i] = 0.f;

    const int g4 = lane >> 2;
    const int l4 = lane & 3;

    // ldmatrix byte addresses
    const uint32_t aL = smb +
        (((wm * 64 + (lane & 15)) * GSTR + ((lane >> 4) << 3)) << 1);
    const uint32_t bL = smb + bsOff +
        (((wn * 64 + (((lane >> 4) & 1) << 3) + (lane & 7)) * GSTR +
          (((lane >> 3) & 1) << 3)) << 1);
    const uint32_t MT16 = (16 * GSTR) << 1;    // 16 rows in bytes

    copy_tile(0, 0);

    const int T = K / 32;
    for (int kt = 0; kt < T; kt++) {
        cp_wait0();
        __syncthreads();
        if (kt + 1 < T) copy_tile((kt + 1) & 1, (kt + 1) * 32);

        const uint32_t ab = aL + (kt & 1) * ABUF;
        const uint32_t bb = bL + (kt & 1) * BBUF;

        #pragma unroll
        for (int ks = 0; ks < 2; ks++) {
            uint32_t afr[4][4], bfr[16];
            #pragma unroll
            for (int mt = 0; mt < 4; mt++)
                ldsm_x4(afr[mt], ab + mt * MT16 + ks * 32);
            #pragma unroll
            for (int ntp = 0; ntp < 4; ntp++)
                ldsm_x4(&bfr[ntp * 4], bb + ntp * MT16 + ks * 32);
            #pragma unroll
            for (int mt = 0; mt < 4; mt++)
                #pragma unroll
                for (int nt = 0; nt < 8; nt++)
                    mma_f16(acc[mt][nt], afr[mt],
                            &bfr[((nt >> 1) << 2) + ((nt & 1) << 1)]);
        }
    }

    #pragma unroll
    for (int nt = 0; nt < 8; nt++) {
        int col = bn + wn * 64 + nt * 8 + l4 * 2;
        float b0 = bias[col], b1 = bias[col + 1];
        #pragma unroll
        for (int mt = 0; mt < 4; mt++) {
            int row = bm + wm * 64 + mt * 16 + g4;
            if (row < Mrows) {
                if (Ch)
                    *reinterpret_cast<uint32_t*>(&Ch[(size_t)row * N + col]) =
                        packh2(acc[mt][nt][0] + b0, acc[mt][nt][1] + b1);
                else {
                    float2 v = make_float2(acc[mt][nt][0] + b0, acc[mt][nt][1] + b1);
                    *reinterpret_cast<float2*>(&Cf[(size_t)row * N + col]) = v;
                }
            }
            if (row + 8 < Mrows) {
                if (Ch)
                    *reinterpret_cast<uint32_t*>(&Ch[(size_t)(row + 8) * N + col]) =
                        packh2(acc[mt][nt][2] + b0, acc[mt][nt][3] + b1);
                else {
                    float2 v = make_float2(acc[mt][nt][2] + b0, acc[mt][nt][3] + b1);
                    *reinterpret_cast<float2*>(&Cf[(size_t)(row + 8) * N + col]) = v;
                }
            }
        }
    }
}

// ---------------------------------------------------------------------------
// fp16 tensor-core flash attention, 512 threads (16 warps), warp = 16 Q rows.
// (unchanged from R9)
// ---------------------------------------------------------------------------
#define AST   72
#define VS_H  (WSIZE * AST)
#define PB_H  (2 * WSIZE * AST)
#define ATTN_SMEM_B ((3 * WSIZE * AST) * 2)   /* 110592 bytes */

__global__ void __launch_bounds__(512)
attn_tc_kernel(const __half* __restrict__ qkv,
               const float* __restrict__ cosb,
               const float* __restrict__ sinb,
               const int* __restrict__ kvidx,
               __half* __restrict__ osc)
{
    extern __shared__ __half shh[];
    __half* Ksm = shh;
    __half* Vsm = shh + VS_H;
    __half* Pbm = shh + PB_H;

    const int w    = blockIdx.x;
    const int h    = blockIdx.y;
    const int tid  = threadIdx.x;
    const int lane = tid & 31;
    const int wid  = tid >> 5;
    const int g4   = lane >> 2;
    const int l4   = lane & 3;
    const int wrow = wid * 16;

    {
        const int row = tid >> 1;
        const int d0  = (tid & 1) * 16;
        const int gi  = w * WSIZE + row;
        const __half* qrow = &qkv[(size_t)gi * QKVN + h * HDIM];
        const __half* krow = qrow + EMBED;
        const __half* vrow = qrow + 2 * EMBED;
        const float* crw  = &cosb[(size_t)gi * HDIM];
        const float* srw  = &sinb[(size_t)gi * HDIM];
        __half* pb = Pbm + row * AST;
        __half* kb = Ksm + row * AST;
        __half* vb = Vsm + row * AST;
        #pragma unroll
        for (int dd = 0; dd < 8; dd++) {
            int d = d0 + dd * 2;
            float2 c   = *reinterpret_cast<const float2*>(crw + d);
            float2 s   = *reinterpret_cast<const float2*>(srw + d);
            float2 qa  = __half22float2(*reinterpret_cast<const __half2*>(qrow + d));
            float2 qb  = __half22float2(*reinterpret_cast<const __half2*>(qrow + d + 32));
            float2 ka  = __half22float2(*reinterpret_cast<const __half2*>(krow + d));
            float2 kb2 = __half22float2(*reinterpret_cast<const __half2*>(krow + d + 32));
            *reinterpret_cast<uint32_t*>(pb + d)      = packh2(qa.x*c.x - qb.x*s.x, qa.y*c.y - qb.y*s.y);
            *reinterpret_cast<uint32_t*>(pb + d + 32) = packh2(qb.x*c.x + qa.x*s.x, qb.y*c.y + qa.y*s.y);
            *reinterpret_cast<uint32_t*>(kb + d)      = packh2(ka.x*c.x - kb2.x*s.x, ka.y*c.y - kb2.y*s.y);
            *reinterpret_cast<uint32_t*>(kb + d + 32) = packh2(kb2.x*c.x + ka.x*s.x, kb2.y*c.y + ka.y*s.y);
            *reinterpret_cast<uint32_t*>(vb + d)      =
                *reinterpret_cast<const uint32_t*>(vrow + d);
            *reinterpret_cast<uint32_t*>(vb + d + 32) =
                *reinterpret_cast<const uint32_t*>(vrow + d + 32);
        }
    }
    __syncthreads();

    const uint32_t ks_b = smem_u32(Ksm);
    const uint32_t vs_b = smem_u32(Vsm);
    const uint32_t pb_b = smem_u32(Pbm);
    const uint32_t ROWB = AST * 2;
    const uint32_t pbA = pb_b +
        (((wrow + (lane & 15)) * AST + ((lane >> 4) << 3)) << 1);
    const uint32_t ksB = ks_b +
        ((((((lane >> 4) & 1) << 3) + (lane & 7)) * AST +
          (((lane >> 3) & 1) << 3)) << 1);
    const uint32_t vsB = vs_b +
        ((((((lane >> 3) & 1) << 3) + (lane & 7)) * AST +
          (((lane >> 4) & 1) << 3)) << 1);

    uint32_t aQ[4][4];
    #pragma unroll
    for (int ks = 0; ks < 4; ks++)
        ldsm_x4(aQ[ks], pbA + ks * 32);
    __syncwarp();

    const float SC = 0.125f * 1.4426950408889634f;

    float mx[2] = {-1e30f, -1e30f}, lsum[2] = {0.f, 0.f};
    float Oacc[8][4];
    #pragma unroll
    for (int nt = 0; nt < 8; nt++)
        #pragma unroll
        for (int i = 0; i < 4; i++) Oacc[nt][i] = 0.f;

    for (int c = 0; c < 4; c++) {
        const int n0 = c * 64;

        float Sacc[8][4];
        #pragma unroll
        for (int nt = 0; nt < 8; nt++)
            #pragma unroll
            for (int i = 0; i < 4; i++) Sacc[nt][i] = 0.f;

        #pragma unroll
        for (int ks = 0; ks < 4; ks++) {
            uint32_t bf[16];
            #pragma unroll
            for (int ntp = 0; ntp < 4; ntp++)
                ldsm_x4(&bf[ntp * 4], ksB + (n0 + ntp * 16) * ROWB + ks * 32);
            #pragma unroll
            for (int nt = 0; nt < 8; nt++)
                mma_f16(Sacc[nt], aQ[ks],
                        &bf[((nt >> 1) << 2) + ((nt & 1) << 1)]);
        }

        #pragma unroll
        for (int hf = 0; hf < 2; hf++) {
            float rm = -1e30f;
            #pragma unroll
            for (int nt = 0; nt < 8; nt++) {
                rm = fmaxf(rm, Sacc[nt][2*hf]);
                rm = fmaxf(rm, Sacc[nt][2*hf+1]);
            }
            rm = fmaxf(rm, __shfl_xor_sync(0xffffffffu, rm, 1));
            rm = fmaxf(rm, __shfl_xor_sync(0xffffffffu, rm, 2));
            float nmx = fmaxf(mx[hf], rm * SC);
            float corr = ex2f(mx[hf] - nmx);
            mx[hf] = nmx;

            float ps = 0.f;
            #pragma unroll
            for (int nt = 0; nt < 8; nt++) {
                float p0 = ex2f(fmaf(Sacc[nt][2*hf],   SC, -nmx));
                float p1 = ex2f(fmaf(Sacc[nt][2*hf+1], SC, -nmx));
                ps += p0 + p1;
                Sacc[nt][2*hf]   = p0;
                Sacc[nt][2*hf+1] = p1;
            }
            ps += __shfl_xor_sync(0xffffffffu, ps, 1);
            ps += __shfl_xor_sync(0xffffffffu, ps, 2);
            lsum[hf] = lsum[hf] * corr + ps;

            #pragma unroll
            for (int nt = 0; nt < 8; nt++) {
                Oacc[nt][2*hf]   *= corr;
                Oacc[nt][2*hf+1] *= corr;
            }
        }

        {
            int r0 = wrow + g4;
            __half* p0r = Pbm + r0 * AST;
            __half* p1r = Pbm + (r0 + 8) * AST;
            #pragma unroll
            for (int nt = 0; nt < 8; nt++) {
                int col = nt * 8 + 2 * l4;
                *reinterpret_cast<uint32_t*>(p0r + col) = packh2(Sacc[nt][0], Sacc[nt][1]);
                *reinterpret_cast<uint32_t*>(p1r + col) = packh2(Sacc[nt][2], Sacc[nt][3]);
            }
        }
        __syncwarp();

        #pragma unroll
        for (int ks = 0; ks < 4; ks++) {
            uint32_t aP[4], bv[16];
            ldsm_x4(aP, pbA + ks * 32);
            #pragma unroll
            for (int ntp = 0; ntp < 4; ntp++)
                ldsm_x4_t(&bv[ntp * 4], vsB + (n0 + ks * 16) * ROWB + ntp * 32);
            #pragma unroll
            for (int nt = 0; nt < 8; nt++)
                mma_f16(Oacc[nt], aP,
                        &bv[((nt >> 1) << 2) + ((nt & 1) << 1)]);
        }
        __syncwarp();
    }

    {
        int r0 = wrow + g4;
        float inv0 = 1.f / lsum[0];
        float inv1 = 1.f / lsum[1];
        int o0 = kvidx[w * WSIZE + r0];
        int o1 = kvidx[w * WSIZE + r0 + 8];
        __half* base0 = &osc[(size_t)o0 * EMBED + h * HDIM];
        __half* base1 = &osc[(size_t)o1 * EMBED + h * HDIM];
        #pragma unroll
        for (int nt = 0; nt < 8; nt++) {
            int col = nt * 8 + 2 * l4;
            *reinterpret_cast<uint32_t*>(base0 + col) =
                packh2(Oacc[nt][0] * inv0, Oacc[nt][1] * inv0);
            *reinterpret_cast<uint32_t*>(base1 + col) =
                packh2(Oacc[nt][2] * inv1, Oacc[nt][3] * inv1);
        }
    }
}

// ---------------------------------------------------------------------------
extern "C" void kernel_launch(void* const* d_in, const int* in_sizes, int n_in,
                              void* d_out, int out_size)
{
    const float* x      = (const float*)d_in[0];
    const float* qkv_w  = (const float*)d_in[1];
    const float* qkv_b  = (const float*)d_in[2];
    const float* proj_w = (const float*)d_in[3];
    const float* proj_b = (const float*)d_in[4];
    const float* rope_c = (const float*)d_in[6];
    const float* rope_s = (const float*)d_in[7];
    const int*   kvi    = (const int*)d_in[8];
    float*       out    = (float*)d_out;

    __half *xh, *wqkv, *wproj, *qkvh, *osch;
    cudaGetSymbolAddress((void**)&xh,    g_xh);
    cudaGetSymbolAddress((void**)&wqkv,  g_wqkv);
    cudaGetSymbolAddress((void**)&wproj, g_wproj);
    cudaGetSymbolAddress((void**)&qkvh,  g_qkvh);
    cudaGetSymbolAddress((void**)&osch,  g_osch);

    // 0) fp32 -> fp16 conversions (x padded with zero row)
    {
        int nx_src = LTOT * EMBED, nx_tot = MTOT * EMBED;
        cvt_kernel<<<(nx_tot / 4 + 255) / 256, 256>>>(x, xh, nx_src, nx_tot);
        int nw = QKVN * EMBED;
        cvt_kernel<<<(nw / 4 + 255) / 256, 256>>>(qkv_w, wqkv, nw, nw);
        int np = EMBED * EMBED;
        cvt_kernel<<<(np / 4 + 255) / 256, 256>>>(proj_w, wproj, np, np);
    }

    cudaFuncSetAttribute(h16_gemm_kernel,
                         cudaFuncAttributeMaxDynamicSharedMemorySize, GEMM_SMEM_B);

    // 1) QKV GEMM with fused row gather (fp16 in, fp16 out)
    {
        dim3 grid(QKVN / 256, MTOT / 128);
        h16_gemm_kernel<<<grid, 256, GEMM_SMEM_B>>>(xh, wqkv, qkv_b, nullptr, qkvh,
                                                    kvi, MTOT, QKVN, EMBED);
    }

    // 2) fp16 tensor-core flash attention (RoPE + scatter fused)
    {
        cudaFuncSetAttribute(attn_tc_kernel,
                             cudaFuncAttributeMaxDynamicSharedMemorySize, ATTN_SMEM_B);
        dim3 grid(NWIN, NHEADS);
        attn_tc_kernel<<<grid, 512, ATTN_SMEM_B>>>(qkvh, rope_c, rope_s, kvi, osch);
    }

    // 3) Output projection (fp16 in, fp32 out)
    {
        dim3 grid(EMBED / 256, (LTOT + 127) / 128);
        h16_gemm_kernel<<<grid, 256, GEMM_SMEM_B>>>(osch, wproj, proj_b, out, nullptr,
                                                    nullptr, LTOT, EMBED, EMBED);
    }
}

// round 11
// speedup vs baseline: 1.2278x; 1.2278x over previous
#include <cuda_runtime.h>
#include <cuda_fp16.h>
#include <cstdint>
#include <cstddef>

#define EMBED    1024
#define NHEADS   16
#define HDIM     64
#define WSIZE    256
#define NWIN     64
#define MTOT     (NWIN*WSIZE)     /* 16384 */
#define LTOT     (MTOT-1)         /* 16383 */
#define QKVN     (3*EMBED)        /* 3072  */

// Scratch (allocation-free rule: __device__ globals)
__device__ __half g_xh[(size_t)MTOT * EMBED];    // x fp16, padding row zeroed
__device__ __half g_wqkv[(size_t)QKVN * EMBED];  // qkv_w fp16
__device__ __half g_wproj[(size_t)EMBED * EMBED];// proj_w fp16
__device__ __half g_qkvh[(size_t)MTOT * QKVN];   // gathered-order qkv fp16
__device__ __half g_osch[(size_t)MTOT * EMBED];  // scattered attention out fp16

__device__ __forceinline__ float ex2f(float x) {
    float y;
    asm("ex2.approx.f32 %0, %1;" : "=f"(y) : "f"(x));
    return y;
}
__device__ __forceinline__ uint32_t packh2(float lo, float hi) {
    __half2 h = __floats2half2_rn(lo, hi);
    return *reinterpret_cast<uint32_t*>(&h);
}
__device__ __forceinline__ void mma_f16(float* c, const uint32_t* a, const uint32_t* b) {
    asm volatile(
        "mma.sync.aligned.m16n8k16.row.col.f32.f16.f16.f32 "
        "{%0,%1,%2,%3}, {%4,%5,%6,%7}, {%8,%9}, {%0,%1,%2,%3};"
        : "+f"(c[0]), "+f"(c[1]), "+f"(c[2]), "+f"(c[3])
        : "r"(a[0]), "r"(a[1]), "r"(a[2]), "r"(a[3]), "r"(b[0]), "r"(b[1]));
}
__device__ __forceinline__ void ldsm_x4(uint32_t* r, uint32_t addr) {
    asm volatile("ldmatrix.sync.aligned.m8n8.x4.shared.b16 {%0,%1,%2,%3}, [%4];"
                 : "=r"(r[0]), "=r"(r[1]), "=r"(r[2]), "=r"(r[3]) : "r"(addr));
}
__device__ __forceinline__ void ldsm_x4_t(uint32_t* r, uint32_t addr) {
    asm volatile("ldmatrix.sync.aligned.m8n8.x4.trans.shared.b16 {%0,%1,%2,%3}, [%4];"
                 : "=r"(r[0]), "=r"(r[1]), "=r"(r[2]), "=r"(r[3]) : "r"(addr));
}
__device__ __forceinline__ uint32_t smem_u32(const void* p) {
    uint32_t a;
    asm("{ .reg .u64 t; cvta.to.shared.u64 t, %1; cvt.u32.u64 %0, t; }"
        : "=r"(a) : "l"(p));
    return a;
}
__device__ __forceinline__ void cp16(uint32_t smem, const void* g) {
    asm volatile("cp.async.cg.shared.global [%0], [%1], 16;" :: "r"(smem), "l"(g));
}
__device__ __forceinline__ void cp_commit() {
    asm volatile("cp.async.commit_group;" ::: "memory");
}
__device__ __forceinline__ void cp_wait1() {
    asm volatile("cp.async.wait_group 1;" ::: "memory");
}
__device__ __forceinline__ void cp_wait0() {
    asm volatile("cp.async.wait_group 0;" ::: "memory");
}

// ---------------------------------------------------------------------------
// fp32 -> fp16 conversion, zero-fills [n_src, n_tot)
// ---------------------------------------------------------------------------
__global__ void cvt_kernel(const float* __restrict__ src, __half* __restrict__ dst,
                           int n_src, int n_tot)
{
    int i = (blockIdx.x * blockDim.x + threadIdx.x) << 2;
    if (i >= n_tot) return;
    uint2 u;
    if (i < n_src) {
        float4 v = *reinterpret_cast<const float4*>(src + i);
        u.x = packh2(v.x, v.y);
        u.y = packh2(v.z, v.w);
    } else {
        u = make_uint2(0u, 0u);
    }
    *reinterpret_cast<uint2*>(dst + i) = u;
}

// ---------------------------------------------------------------------------
// fp16 tensor-core GEMM (fp32 accum), cp.async 3-stage pipeline:
//   C[m][n] = sum_k A[row(m)][k] * B[n][k] + bias[n]
//   BM=BN=128, BK=32 halves. 256 threads, 8 warps (4x2), warp tile 32x64.
//   122 regs -> 2 blocks/SM; smem 61440 B (3 stages) -> 2 blocks fit.
// ---------------------------------------------------------------------------
#define GSTR     40                   /* halves per smem row  */
#define TILE_HH  (128 * GSTR)         /* 5120 halves per tile */
#define TILE_BB  (TILE_HH * 2)        /* 10240 bytes          */
#define NSTAGE   3
#define GEMM_SMEM_B (2 * NSTAGE * TILE_BB)    /* 61440 B */

__global__ void __launch_bounds__(256, 2)
h16_gemm_kernel(const __half* __restrict__ A,
                const __half* __restrict__ B,
                const float* __restrict__ bias,
                float* __restrict__ Cf,
                __half* __restrict__ Ch,
                const int* __restrict__ gidx,
                int Mrows, int N, int K)
{
    extern __shared__ __half smh[];
    // layout: As[3][128][40], Bs[3][128][40]
    __shared__ int arow[128];

    const int tid  = threadIdx.x;
    const int lane = tid & 31;
    const int wid  = tid >> 5;
    const int wm   = wid & 3;
    const int wn   = wid >> 2;
    const int bm   = blockIdx.y * 128;
    const int bn   = blockIdx.x * 128;

    if (tid < 128) {
        int m = bm + tid;
        arow[tid] = (m < Mrows) ? (gidx ? gidx[m] : m) : 0;
    }
    __syncthreads();

    const uint32_t smb   = smem_u32(smh);
    const uint32_t bsOff = NSTAGE * TILE_BB;      // byte offset of Bs region

    // cp.async mapping: 512 16B-chunks per tile; chunk c -> row=c>>2, col=(c&3)*8
    const int crow = tid >> 2;            // rows 0..63 (+64 second pass)
    const int ccol = (tid & 3) << 3;      // 0,8,16,24 halves

    auto copy_tile = [&](int s, int k0) {
        uint32_t abase = smb + s * TILE_BB + ((crow * GSTR + ccol) << 1);
        uint32_t bbase = abase + bsOff;
        #pragma unroll
        for (int i = 0; i < 2; i++) {
            int row = crow + i * 64;
            uint32_t off = (uint32_t)(i * 64 * GSTR) << 1;
            cp16(abase + off, &A[(size_t)arow[row] * K + k0 + ccol]);
            cp16(bbase + off, &B[(size_t)(bn + row) * K + k0 + ccol]);
        }
        cp_commit();
    };

    float acc[2][8][4];
    #pragma unroll
    for (int mt = 0; mt < 2; mt++)
        #pragma unroll
        for (int nt = 0; nt < 8; nt++)
            #pragma unroll
            for (int i = 0; i < 4; i++) acc[mt][nt][i] = 0.f;

    const int g4 = lane >> 2;
    const int l4 = lane & 3;

    // ldmatrix byte addresses
    const uint32_t aL = smb +
        (((wm * 32 + (lane & 15)) * GSTR + ((lane >> 4) << 3)) << 1);
    const uint32_t bL = smb + bsOff +
        (((wn * 64 + (((lane >> 4) & 1) << 3) + (lane & 7)) * GSTR +
          (((lane >> 3) & 1) << 3)) << 1);
    const uint32_t MT16 = (16 * GSTR) << 1;   // 16 rows in bytes

    const int T = K / 32;
    copy_tile(0, 0);
    if (T > 1) copy_tile(1, 32);

    for (int kt = 0; kt < T; kt++) {
        const int s = kt % NSTAGE;
        if (kt + 2 < T) cp_wait1(); else cp_wait0();
        __syncthreads();
        if (kt + 2 < T) copy_tile((kt + 2) % NSTAGE, (kt + 2) * 32);

        const uint32_t ab = aL + s * TILE_BB;
        const uint32_t bb = bL + s * TILE_BB;

        #pragma unroll
        for (int ks = 0; ks < 2; ks++) {
            uint32_t afr[2][4], bfr[16];
            ldsm_x4(afr[0], ab + ks * 32);
            ldsm_x4(afr[1], ab + MT16 + ks * 32);
            #pragma unroll
            for (int ntp = 0; ntp < 4; ntp++)
                ldsm_x4(&bfr[ntp * 4], bb + ntp * MT16 + ks * 32);
            #pragma unroll
            for (int mt = 0; mt < 2; mt++)
                #pragma unroll
                for (int nt = 0; nt < 8; nt++)
                    mma_f16(acc[mt][nt], afr[mt],
                            &bfr[((nt >> 1) << 2) + ((nt & 1) << 1)]);
        }
        __syncthreads();
    }

    #pragma unroll
    for (int nt = 0; nt < 8; nt++) {
        int col = bn + wn * 64 + nt * 8 + l4 * 2;
        float b0 = bias[col], b1 = bias[col + 1];
        #pragma unroll
        for (int mt = 0; mt < 2; mt++) {
            int row = bm + wm * 32 + mt * 16 + g4;
            if (row < Mrows) {
                if (Ch)
                    *reinterpret_cast<uint32_t*>(&Ch[(size_t)row * N + col]) =
                        packh2(acc[mt][nt][0] + b0, acc[mt][nt][1] + b1);
                else {
                    float2 v = make_float2(acc[mt][nt][0] + b0, acc[mt][nt][1] + b1);
                    *reinterpret_cast<float2*>(&Cf[(size_t)row * N + col]) = v;
                }
            }
            if (row + 8 < Mrows) {
                if (Ch)
                    *reinterpret_cast<uint32_t*>(&Ch[(size_t)(row + 8) * N + col]) =
                        packh2(acc[mt][nt][2] + b0, acc[mt][nt][3] + b1);
                else {
                    float2 v = make_float2(acc[mt][nt][2] + b0, acc[mt][nt][3] + b1);
                    *reinterpret_cast<float2*>(&Cf[(size_t)(row + 8) * N + col]) = v;
                }
            }
        }
    }
}

// ---------------------------------------------------------------------------
// fp16 tensor-core flash attention, 512 threads (16 warps), warp = 16 Q rows.
// (unchanged from R9)
// ---------------------------------------------------------------------------
#define AST   72
#define VS_H  (WSIZE * AST)
#define PB_H  (2 * WSIZE * AST)
#define ATTN_SMEM_B ((3 * WSIZE * AST) * 2)   /* 110592 bytes */

__global__ void __launch_bounds__(512)
attn_tc_kernel(const __half* __restrict__ qkv,
               const float* __restrict__ cosb,
               const float* __restrict__ sinb,
               const int* __restrict__ kvidx,
               __half* __restrict__ osc)
{
    extern __shared__ __half shh[];
    __half* Ksm = shh;
    __half* Vsm = shh + VS_H;
    __half* Pbm = shh + PB_H;

    const int w    = blockIdx.x;
    const int h    = blockIdx.y;
    const int tid  = threadIdx.x;
    const int lane = tid & 31;
    const int wid  = tid >> 5;
    const int g4   = lane >> 2;
    const int l4   = lane & 3;
    const int wrow = wid * 16;

    {
        const int row = tid >> 1;
        const int d0  = (tid & 1) * 16;
        const int gi  = w * WSIZE + row;
        const __half* qrow = &qkv[(size_t)gi * QKVN + h * HDIM];
        const __half* krow = qrow + EMBED;
        const __half* vrow = qrow + 2 * EMBED;
        const float* crw  = &cosb[(size_t)gi * HDIM];
        const float* srw  = &sinb[(size_t)gi * HDIM];
        __half* pb = Pbm + row * AST;
        __half* kb = Ksm + row * AST;
        __half* vb = Vsm + row * AST;
        #pragma unroll
        for (int dd = 0; dd < 8; dd++) {
            int d = d0 + dd * 2;
            float2 c   = *reinterpret_cast<const float2*>(crw + d);
            float2 s   = *reinterpret_cast<const float2*>(srw + d);
            float2 qa  = __half22float2(*reinterpret_cast<const __half2*>(qrow + d));
            float2 qb  = __half22float2(*reinterpret_cast<const __half2*>(qrow + d + 32));
            float2 ka  = __half22float2(*reinterpret_cast<const __half2*>(krow + d));
            float2 kb2 = __half22float2(*reinterpret_cast<const __half2*>(krow + d + 32));
            *reinterpret_cast<uint32_t*>(pb + d)      = packh2(qa.x*c.x - qb.x*s.x, qa.y*c.y - qb.y*s.y);
            *reinterpret_cast<uint32_t*>(pb + d + 32) = packh2(qb.x*c.x + qa.x*s.x, qb.y*c.y + qa.y*s.y);
            *reinterpret_cast<uint32_t*>(kb + d)      = packh2(ka.x*c.x - kb2.x*s.x, ka.y*c.y - kb2.y*s.y);
            *reinterpret_cast<uint32_t*>(kb + d + 32) = packh2(kb2.x*c.x + ka.x*s.x, kb2.y*c.y + ka.y*s.y);
            *reinterpret_cast<uint32_t*>(vb + d)      =
                *reinterpret_cast<const uint32_t*>(vrow + d);
            *reinterpret_cast<uint32_t*>(vb + d + 32) =
                *reinterpret_cast<const uint32_t*>(vrow + d + 32);
        }
    }
    __syncthreads();

    const uint32_t ks_b = smem_u32(Ksm);
    const uint32_t vs_b = smem_u32(Vsm);
    const uint32_t pb_b = smem_u32(Pbm);
    const uint32_t ROWB = AST * 2;
    const uint32_t pbA = pb_b +
        (((wrow + (lane & 15)) * AST + ((lane >> 4) << 3)) << 1);
    const uint32_t ksB = ks_b +
        ((((((lane >> 4) & 1) << 3) + (lane & 7)) * AST +
          (((lane >> 3) & 1) << 3)) << 1);
    const uint32_t vsB = vs_b +
        ((((((lane >> 3) & 1) << 3) + (lane & 7)) * AST +
          (((lane >> 4) & 1) << 3)) << 1);

    uint32_t aQ[4][4];
    #pragma unroll
    for (int ks = 0; ks < 4; ks++)
        ldsm_x4(aQ[ks], pbA + ks * 32);
    __syncwarp();

    const float SC = 0.125f * 1.4426950408889634f;

    float mx[2] = {-1e30f, -1e30f}, lsum[2] = {0.f, 0.f};
    float Oacc[8][4];
    #pragma unroll
    for (int nt = 0; nt < 8; nt++)
        #pragma unroll
        for (int i = 0; i < 4; i++) Oacc[nt][i] = 0.f;

    for (int c = 0; c < 4; c++) {
        const int n0 = c * 64;

        float Sacc[8][4];
        #pragma unroll
        for (int nt = 0; nt < 8; nt++)
            #pragma unroll
            for (int i = 0; i < 4; i++) Sacc[nt][i] = 0.f;

        #pragma unroll
        for (int ks = 0; ks < 4; ks++) {
            uint32_t bf[16];
            #pragma unroll
            for (int ntp = 0; ntp < 4; ntp++)
                ldsm_x4(&bf[ntp * 4], ksB + (n0 + ntp * 16) * ROWB + ks * 32);
            #pragma unroll
            for (int nt = 0; nt < 8; nt++)
                mma_f16(Sacc[nt], aQ[ks],
                        &bf[((nt >> 1) << 2) + ((nt & 1) << 1)]);
        }

        #pragma unroll
        for (int hf = 0; hf < 2; hf++) {
            float rm = -1e30f;
            #pragma unroll
            for (int nt = 0; nt < 8; nt++) {
                rm = fmaxf(rm, Sacc[nt][2*hf]);
                rm = fmaxf(rm, Sacc[nt][2*hf+1]);
            }
            rm = fmaxf(rm, __shfl_xor_sync(0xffffffffu, rm, 1));
            rm = fmaxf(rm, __shfl_xor_sync(0xffffffffu, rm, 2));
            float nmx = fmaxf(mx[hf], rm * SC);
            float corr = ex2f(mx[hf] - nmx);
            mx[hf] = nmx;

            float ps = 0.f;
            #pragma unroll
            for (int nt = 0; nt < 8; nt++) {
                float p0 = ex2f(fmaf(Sacc[nt][2*hf],   SC, -nmx));
                float p1 = ex2f(fmaf(Sacc[nt][2*hf+1], SC, -nmx));
                ps += p0 + p1;
                Sacc[nt][2*hf]   = p0;
                Sacc[nt][2*hf+1] = p1;
            }
            ps += __shfl_xor_sync(0xffffffffu, ps, 1);
            ps += __shfl_xor_sync(0xffffffffu, ps, 2);
            lsum[hf] = lsum[hf] * corr + ps;

            #pragma unroll
            for (int nt = 0; nt < 8; nt++) {
                Oacc[nt][2*hf]   *= corr;
                Oacc[nt][2*hf+1] *= corr;
            }
        }

        {
            int r0 = wrow + g4;
            __half* p0r = Pbm + r0 * AST;
            __half* p1r = Pbm + (r0 + 8) * AST;
            #pragma unroll
            for (int nt = 0; nt < 8; nt++) {
                int col = nt * 8 + 2 * l4;
                *reinterpret_cast<uint32_t*>(p0r + col) = packh2(Sacc[nt][0], Sacc[nt][1]);
                *reinterpret_cast<uint32_t*>(p1r + col) = packh2(Sacc[nt][2], Sacc[nt][3]);
            }
        }
        __syncwarp();

        #pragma unroll
        for (int ks = 0; ks < 4; ks++) {
            uint32_t aP[4], bv[16];
            ldsm_x4(aP, pbA + ks * 32);
            #pragma unroll
            for (int ntp = 0; ntp < 4; ntp++)
                ldsm_x4_t(&bv[ntp * 4], vsB + (n0 + ks * 16) * ROWB + ntp * 32);
            #pragma unroll
            for (int nt = 0; nt < 8; nt++)
                mma_f16(Oacc[nt], aP,
                        &bv[((nt >> 1) << 2) + ((nt & 1) << 1)]);
        }
        __syncwarp();
    }

    {
        int r0 = wrow + g4;
        float inv0 = 1.f / lsum[0];
        float inv1 = 1.f / lsum[1];
        int o0 = kvidx[w * WSIZE + r0];
        int o1 = kvidx[w * WSIZE + r0 + 8];
        __half* base0 = &osc[(size_t)o0 * EMBED + h * HDIM];
        __half* base1 = &osc[(size_t)o1 * EMBED + h * HDIM];
        #pragma unroll
        for (int nt = 0; nt < 8; nt++) {
            int col = nt * 8 + 2 * l4;
            *reinterpret_cast<uint32_t*>(base0 + col) =
                packh2(Oacc[nt][0] * inv0, Oacc[nt][1] * inv0);
            *reinterpret_cast<uint32_t*>(base1 + col) =
                packh2(Oacc[nt][2] * inv1, Oacc[nt][3] * inv1);
        }
    }
}

// ---------------------------------------------------------------------------
extern "C" void kernel_launch(void* const* d_in, const int* in_sizes, int n_in,
                              void* d_out, int out_size)
{
    const float* x      = (const float*)d_in[0];
    const float* qkv_w  = (const float*)d_in[1];
    const float* qkv_b  = (const float*)d_in[2];
    const float* proj_w = (const float*)d_in[3];
    const float* proj_b = (const float*)d_in[4];
    const float* rope_c = (const float*)d_in[6];
    const float* rope_s = (const float*)d_in[7];
    const int*   kvi    = (const int*)d_in[8];
    float*       out    = (float*)d_out;

    __half *xh, *wqkv, *wproj, *qkvh, *osch;
    cudaGetSymbolAddress((void**)&xh,    g_xh);
    cudaGetSymbolAddress((void**)&wqkv,  g_wqkv);
    cudaGetSymbolAddress((void**)&wproj, g_wproj);
    cudaGetSymbolAddress((void**)&qkvh,  g_qkvh);
    cudaGetSymbolAddress((void**)&osch,  g_osch);

    // 0) fp32 -> fp16 conversions (x padded with zero row)
    {
        int nx_src = LTOT * EMBED, nx_tot = MTOT * EMBED;
        cvt_kernel<<<(nx_tot / 4 + 255) / 256, 256>>>(x, xh, nx_src, nx_tot);
        int nw = QKVN * EMBED;
        cvt_kernel<<<(nw / 4 + 255) / 256, 256>>>(qkv_w, wqkv, nw, nw);
        int np = EMBED * EMBED;
        cvt_kernel<<<(np / 4 + 255) / 256, 256>>>(proj_w, wproj, np, np);
    }

    cudaFuncSetAttribute(h16_gemm_kernel,
                         cudaFuncAttributeMaxDynamicSharedMemorySize, GEMM_SMEM_B);

    // 1) QKV GEMM with fused row gather (fp16 in, fp16 out)
    {
        dim3 grid(QKVN / 128, MTOT / 128);
        h16_gemm_kernel<<<grid, 256, GEMM_SMEM_B>>>(xh, wqkv, qkv_b, nullptr, qkvh,
                                                    kvi, MTOT, QKVN, EMBED);
    }

    // 2) fp16 tensor-core flash attention (RoPE + scatter fused)
    {
        cudaFuncSetAttribute(attn_tc_kernel,
                             cudaFuncAttributeMaxDynamicSharedMemorySize, ATTN_SMEM_B);
        dim3 grid(NWIN, NHEADS);
        attn_tc_kernel<<<grid, 512, ATTN_SMEM_B>>>(qkvh, rope_c, rope_s, kvi, osch);
    }

    // 3) Output projection (fp16 in, fp32 out)
    {
        dim3 grid(EMBED / 128, (LTOT + 127) / 128);
        h16_gemm_kernel<<<grid, 256, GEMM_SMEM_B>>>(osch, wproj, proj_b, out, nullptr,
                                                    nullptr, LTOT, EMBED, EMBED);
    }
}

// round 13
// speedup vs baseline: 1.2833x; 1.0452x over previous
#include <cuda_runtime.h>
#include <cuda_fp16.h>
#include <cstdint>
#include <cstddef>

#define EMBED    1024
#define NHEADS   16
#define HDIM     64
#define WSIZE    256
#define NWIN     64
#define MTOT     (NWIN*WSIZE)     /* 16384 */
#define LTOT     (MTOT-1)         /* 16383 */
#define QKVN     (3*EMBED)        /* 3072  */

// Scratch (allocation-free rule: __device__ globals)
__device__ __half g_xh[(size_t)MTOT * EMBED];    // x fp16, padding row zeroed
__device__ __half g_wqkv[(size_t)QKVN * EMBED];  // qkv_w fp16
__device__ __half g_wproj[(size_t)EMBED * EMBED];// proj_w fp16
__device__ __half g_qkvh[(size_t)MTOT * QKVN];   // gathered-order qkv fp16
__device__ __half g_osch[(size_t)MTOT * EMBED];  // scattered attention out fp16

__device__ __forceinline__ float ex2f(float x) {
    float y;
    asm("ex2.approx.f32 %0, %1;" : "=f"(y) : "f"(x));
    return y;
}
__device__ __forceinline__ uint32_t packh2(float lo, float hi) {
    __half2 h = __floats2half2_rn(lo, hi);
    return *reinterpret_cast<uint32_t*>(&h);
}
__device__ __forceinline__ void mma_f16(float* c, const uint32_t* a, const uint32_t* b) {
    asm volatile(
        "mma.sync.aligned.m16n8k16.row.col.f32.f16.f16.f32 "
        "{%0,%1,%2,%3}, {%4,%5,%6,%7}, {%8,%9}, {%0,%1,%2,%3};"
        : "+f"(c[0]), "+f"(c[1]), "+f"(c[2]), "+f"(c[3])
        : "r"(a[0]), "r"(a[1]), "r"(a[2]), "r"(a[3]), "r"(b[0]), "r"(b[1]));
}
__device__ __forceinline__ void ldsm_x4(uint32_t* r, uint32_t addr) {
    asm volatile("ldmatrix.sync.aligned.m8n8.x4.shared.b16 {%0,%1,%2,%3}, [%4];"
                 : "=r"(r[0]), "=r"(r[1]), "=r"(r[2]), "=r"(r[3]) : "r"(addr));
}
__device__ __forceinline__ void ldsm_x4_t(uint32_t* r, uint32_t addr) {
    asm volatile("ldmatrix.sync.aligned.m8n8.x4.trans.shared.b16 {%0,%1,%2,%3}, [%4];"
                 : "=r"(r[0]), "=r"(r[1]), "=r"(r[2]), "=r"(r[3]) : "r"(addr));
}
__device__ __forceinline__ uint32_t smem_u32(const void* p) {
    uint32_t a;
    asm("{ .reg .u64 t; cvta.to.shared.u64 t, %1; cvt.u32.u64 %0, t; }"
        : "=r"(a) : "l"(p));
    return a;
}
__device__ __forceinline__ void cp16(uint32_t smem, const void* g) {
    asm volatile("cp.async.cg.shared.global [%0], [%1], 16;" :: "r"(smem), "l"(g));
}
__device__ __forceinline__ void cp_commit() {
    asm volatile("cp.async.commit_group;" ::: "memory");
}
__device__ __forceinline__ void cp_wait1() {
    asm volatile("cp.async.wait_group 1;" ::: "memory");
}
__device__ __forceinline__ void cp_wait0() {
    asm volatile("cp.async.wait_group 0;" ::: "memory");
}

// ---------------------------------------------------------------------------
// fp32 -> fp16 conversion, zero-fills [n_src, n_tot)
// ---------------------------------------------------------------------------
__global__ void cvt_kernel(const float* __restrict__ src, __half* __restrict__ dst,
                           int n_src, int n_tot)
{
    int i = (blockIdx.x * blockDim.x + threadIdx.x) << 2;
    if (i >= n_tot) return;
    uint2 u;
    if (i < n_src) {
        float4 v = *reinterpret_cast<const float4*>(src + i);
        u.x = packh2(v.x, v.y);
        u.y = packh2(v.z, v.w);
    } else {
        u = make_uint2(0u, 0u);
    }
    *reinterpret_cast<uint2*>(dst + i) = u;
}

// ---------------------------------------------------------------------------
// fp16 tensor-core GEMM (fp32 accum), cp.async 3-stage pipeline, BK=64:
//   C[m][n] = sum_k A[row(m)][k] * B[n][k] + bias[n]
//   BM=BN=128. 256 threads, 8 warps (4x2), warp tile 32x64.
//   One __syncthreads per BK=64 iteration (16 total for K=1024).
// ---------------------------------------------------------------------------
#define GSTR     72                   /* halves per smem row (64 + 8 pad) */
#define TILE_HH  (128 * GSTR)         /* 9216 halves per tile */
#define TILE_BB  (TILE_HH * 2)        /* 18432 bytes          */
#define NSTAGE   3
#define GEMM_SMEM_B (2 * NSTAGE * TILE_BB)    /* 110592 B */

__global__ void __launch_bounds__(256, 2)
h16_gemm_kernel(const __half* __restrict__ A,
                const __half* __restrict__ B,
                const float* __restrict__ bias,
                float* __restrict__ Cf,
                __half* __restrict__ Ch,
                const int* __restrict__ gidx,
                int Mrows, int N, int K)
{
    extern __shared__ __half smh[];
    // layout: As[3][128][72], Bs[3][128][72]
    __shared__ int arow[128];

    const int tid  = threadIdx.x;
    const int lane = tid & 31;
    const int wid  = tid >> 5;
    const int wm   = wid & 3;
    const int wn   = wid >> 2;
    const int bm   = blockIdx.y * 128;
    const int bn   = blockIdx.x * 128;

    if (tid < 128) {
        int m = bm + tid;
        arow[tid] = (m < Mrows) ? (gidx ? gidx[m] : m) : 0;
    }
    __syncthreads();

    const uint32_t smb   = smem_u32(smh);
    const uint32_t bsOff = NSTAGE * TILE_BB;      // byte offset of Bs region

    // copy mapping: 1024 16B-chunks per tile; chunk c -> row=c>>3, col=(c&7)*8
    const int crow = tid >> 3;            // rows 0..31 (+32 per pass, 4 passes)
    const int ccol = (tid & 7) << 3;      // halves 0,8,...,56

    auto copy_tile = [&](int s, int k0) {
        uint32_t abase = smb + s * TILE_BB + ((crow * GSTR + ccol) << 1);
        uint32_t bbase = abase + bsOff;
        #pragma unroll
        for (int i = 0; i < 4; i++) {
            int row = crow + i * 32;
            uint32_t off = (uint32_t)(i * 32 * GSTR) << 1;
            cp16(abase + off, &A[(size_t)arow[row] * K + k0 + ccol]);
            cp16(bbase + off, &B[(size_t)(bn + row) * K + k0 + ccol]);
        }
        cp_commit();
    };

    float acc[2][8][4];
    #pragma unroll
    for (int mt = 0; mt < 2; mt++)
        #pragma unroll
        for (int nt = 0; nt < 8; nt++)
            #pragma unroll
            for (int i = 0; i < 4; i++) acc[mt][nt][i] = 0.f;

    const int g4 = lane >> 2;
    const int l4 = lane & 3;

    // ldmatrix byte addresses (stride-72 rows: 4r-bank rotation, conflict-free)
    const uint32_t aL = smb +
        (((wm * 32 + (lane & 15)) * GSTR + ((lane >> 4) << 3)) << 1);
    const uint32_t bL = smb + bsOff +
        (((wn * 64 + (((lane >> 4) & 1) << 3) + (lane & 7)) * GSTR +
          (((lane >> 3) & 1) << 3)) << 1);
    const uint32_t MT16 = (16 * GSTR) << 1;   // 16 rows in bytes

    const int T = K / 64;
    copy_tile(0, 0);
    if (T > 1) copy_tile(1, 64);

    for (int kt = 0; kt < T; kt++) {
        const int s = kt % NSTAGE;
        if (kt + 2 < T) cp_wait1(); else cp_wait0();
        __syncthreads();
        if (kt + 2 < T) copy_tile((kt + 2) % NSTAGE, (kt + 2) * 64);

        const uint32_t ab = aL + s * TILE_BB;
        const uint32_t bb = bL + s * TILE_BB;

        #pragma unroll
        for (int ks = 0; ks < 4; ks++) {
            uint32_t afr[2][4], bfr[16];
            ldsm_x4(afr[0], ab + ks * 32);
            ldsm_x4(afr[1], ab + MT16 + ks * 32);
            #pragma unroll
            for (int ntp = 0; ntp < 4; ntp++)
                ldsm_x4(&bfr[ntp * 4], bb + ntp * MT16 + ks * 32);
            #pragma unroll
            for (int mt = 0; mt < 2; mt++)
                #pragma unroll
                for (int nt = 0; nt < 8; nt++)
                    mma_f16(acc[mt][nt], afr[mt],
                            &bfr[((nt >> 1) << 2) + ((nt & 1) << 1)]);
        }
        // no trailing sync: stage written at kt+1 is the one read at kt,
        // and the top-of-loop barrier at kt+1 orders all reads before it.
    }

    #pragma unroll
    for (int nt = 0; nt < 8; nt++) {
        int col = bn + wn * 64 + nt * 8 + l4 * 2;
        float b0 = bias[col], b1 = bias[col + 1];
        #pragma unroll
        for (int mt = 0; mt < 2; mt++) {
            int row = bm + wm * 32 + mt * 16 + g4;
            if (row < Mrows) {
                if (Ch)
                    *reinterpret_cast<uint32_t*>(&Ch[(size_t)row * N + col]) =
                        packh2(acc[mt][nt][0] + b0, acc[mt][nt][1] + b1);
                else {
                    float2 v = make_float2(acc[mt][nt][0] + b0, acc[mt][nt][1] + b1);
                    *reinterpret_cast<float2*>(&Cf[(size_t)row * N + col]) = v;
                }
            }
            if (row + 8 < Mrows) {
                if (Ch)
                    *reinterpret_cast<uint32_t*>(&Ch[(size_t)(row + 8) * N + col]) =
                        packh2(acc[mt][nt][2] + b0, acc[mt][nt][3] + b1);
                else {
                    float2 v = make_float2(acc[mt][nt][2] + b0, acc[mt][nt][3] + b1);
                    *reinterpret_cast<float2*>(&Cf[(size_t)(row + 8) * N + col]) = v;
                }
            }
        }
    }
}

// ---------------------------------------------------------------------------
// fp16 tensor-core flash attention, 512 threads (16 warps), warp = 16 Q rows.
// (unchanged from R11 best)
// ---------------------------------------------------------------------------
#define AST   72
#define VS_H  (WSIZE * AST)
#define PB_H  (2 * WSIZE * AST)
#define ATTN_SMEM_B ((3 * WSIZE * AST) * 2)   /* 110592 bytes */

__global__ void __launch_bounds__(512)
attn_tc_kernel(const __half* __restrict__ qkv,
               const float* __restrict__ cosb,
               const float* __restrict__ sinb,
               const int* __restrict__ kvidx,
               __half* __restrict__ osc)
{
    extern __shared__ __half shh[];
    __half* Ksm = shh;
    __half* Vsm = shh + VS_H;
    __half* Pbm = shh + PB_H;

    const int w    = blockIdx.x;
    const int h    = blockIdx.y;
    const int tid  = threadIdx.x;
    const int lane = tid & 31;
    const int wid  = tid >> 5;
    const int g4   = lane >> 2;
    const int l4   = lane & 3;
    const int wrow = wid * 16;

    {
        const int row = tid >> 1;
        const int d0  = (tid & 1) * 16;
        const int gi  = w * WSIZE + row;
        const __half* qrow = &qkv[(size_t)gi * QKVN + h * HDIM];
        const __half* krow = qrow + EMBED;
        const __half* vrow = qrow + 2 * EMBED;
        const float* crw  = &cosb[(size_t)gi * HDIM];
        const float* srw  = &sinb[(size_t)gi * HDIM];
        __half* pb = Pbm + row * AST;
        __half* kb = Ksm + row * AST;
        __half* vb = Vsm + row * AST;
        #pragma unroll
        for (int dd = 0; dd < 8; dd++) {
            int d = d0 + dd * 2;
            float2 c   = *reinterpret_cast<const float2*>(crw + d);
            float2 s   = *reinterpret_cast<const float2*>(srw + d);
            float2 qa  = __half22float2(*reinterpret_cast<const __half2*>(qrow + d));
            float2 qb  = __half22float2(*reinterpret_cast<const __half2*>(qrow + d + 32));
            float2 ka  = __half22float2(*reinterpret_cast<const __half2*>(krow + d));
            float2 kb2 = __half22float2(*reinterpret_cast<const __half2*>(krow + d + 32));
            *reinterpret_cast<uint32_t*>(pb + d)      = packh2(qa.x*c.x - qb.x*s.x, qa.y*c.y - qb.y*s.y);
            *reinterpret_cast<uint32_t*>(pb + d + 32) = packh2(qb.x*c.x + qa.x*s.x, qb.y*c.y + qa.y*s.y);
            *reinterpret_cast<uint32_t*>(kb + d)      = packh2(ka.x*c.x - kb2.x*s.x, ka.y*c.y - kb2.y*s.y);
            *reinterpret_cast<uint32_t*>(kb + d + 32) = packh2(kb2.x*c.x + ka.x*s.x, kb2.y*c.y + ka.y*s.y);
            *reinterpret_cast<uint32_t*>(vb + d)      =
                *reinterpret_cast<const uint32_t*>(vrow + d);
            *reinterpret_cast<uint32_t*>(vb + d + 32) =
                *reinterpret_cast<const uint32_t*>(vrow + d + 32);
        }
    }
    __syncthreads();

    const uint32_t ks_b = smem_u32(Ksm);
    const uint32_t vs_b = smem_u32(Vsm);
    const uint32_t pb_b = smem_u32(Pbm);
    const uint32_t ROWB = AST * 2;
    const uint32_t pbA = pb_b +
        (((wrow + (lane & 15)) * AST + ((lane >> 4) << 3)) << 1);
    const uint32_t ksB = ks_b +
        ((((((lane >> 4) & 1) << 3) + (lane & 7)) * AST +
          (((lane >> 3) & 1) << 3)) << 1);
    const uint32_t vsB = vs_b +
        ((((((lane >> 3) & 1) << 3) + (lane & 7)) * AST +
          (((lane >> 4) & 1) << 3)) << 1);

    uint32_t aQ[4][4];
    #pragma unroll
    for (int ks = 0; ks < 4; ks++)
        ldsm_x4(aQ[ks], pbA + ks * 32);
    __syncwarp();

    const float SC = 0.125f * 1.4426950408889634f;

    float mx[2] = {-1e30f, -1e30f}, lsum[2] = {0.f, 0.f};
    float Oacc[8][4];
    #pragma unroll
    for (int nt = 0; nt < 8; nt++)
        #pragma unroll
        for (int i = 0; i < 4; i++) Oacc[nt][i] = 0.f;

    for (int c = 0; c < 4; c++) {
        const int n0 = c * 64;

        float Sacc[8][4];
        #pragma unroll
        for (int nt = 0; nt < 8; nt++)
            #pragma unroll
            for (int i = 0; i < 4; i++) Sacc[nt][i] = 0.f;

        #pragma unroll
        for (int ks = 0; ks < 4; ks++) {
            uint32_t bf[16];
            #pragma unroll
            for (int ntp = 0; ntp < 4; ntp++)
                ldsm_x4(&bf[ntp * 4], ksB + (n0 + ntp * 16) * ROWB + ks * 32);
            #pragma unroll
            for (int nt = 0; nt < 8; nt++)
                mma_f16(Sacc[nt], aQ[ks],
                        &bf[((nt >> 1) << 2) + ((nt & 1) << 1)]);
        }

        #pragma unroll
        for (int hf = 0; hf < 2; hf++) {
            float rm = -1e30f;
            #pragma unroll
            for (int nt = 0; nt < 8; nt++) {
                rm = fmaxf(rm, Sacc[nt][2*hf]);
                rm = fmaxf(rm, Sacc[nt][2*hf+1]);
            }
            rm = fmaxf(rm, __shfl_xor_sync(0xffffffffu, rm, 1));
            rm = fmaxf(rm, __shfl_xor_sync(0xffffffffu, rm, 2));
            float nmx = fmaxf(mx[hf], rm * SC);
            float corr = ex2f(mx[hf] - nmx);
            mx[hf] = nmx;

            float ps = 0.f;
            #pragma unroll
            for (int nt = 0; nt < 8; nt++) {
                float p0 = ex2f(fmaf(Sacc[nt][2*hf],   SC, -nmx));
                float p1 = ex2f(fmaf(Sacc[nt][2*hf+1], SC, -nmx));
                ps += p0 + p1;
                Sacc[nt][2*hf]   = p0;
                Sacc[nt][2*hf+1] = p1;
            }
            ps += __shfl_xor_sync(0xffffffffu, ps, 1);
            ps += __shfl_xor_sync(0xffffffffu, ps, 2);
            lsum[hf] = lsum[hf] * corr + ps;

            #pragma unroll
            for (int nt = 0; nt < 8; nt++) {
                Oacc[nt][2*hf]   *= corr;
                Oacc[nt][2*hf+1] *= corr;
            }
        }

        {
            int r0 = wrow + g4;
            __half* p0r = Pbm + r0 * AST;
            __half* p1r = Pbm + (r0 + 8) * AST;
            #pragma unroll
            for (int nt = 0; nt < 8; nt++) {
                int col = nt * 8 + 2 * l4;
                *reinterpret_cast<uint32_t*>(p0r + col) = packh2(Sacc[nt][0], Sacc[nt][1]);
                *reinterpret_cast<uint32_t*>(p1r + col) = packh2(Sacc[nt][2], Sacc[nt][3]);
            }
        }
        __syncwarp();

        #pragma unroll
        for (int ks = 0; ks < 4; ks++) {
            uint32_t aP[4], bv[16];
            ldsm_x4(aP, pbA + ks * 32);
            #pragma unroll
            for (int ntp = 0; ntp < 4; ntp++)
                ldsm_x4_t(&bv[ntp * 4], vsB + (n0 + ks * 16) * ROWB + ntp * 32);
            #pragma unroll
            for (int nt = 0; nt < 8; nt++)
                mma_f16(Oacc[nt], aP,
                        &bv[((nt >> 1) << 2) + ((nt & 1) << 1)]);
        }
        __syncwarp();
    }

    {
        int r0 = wrow + g4;
        float inv0 = 1.f / lsum[0];
        float inv1 = 1.f / lsum[1];
        int o0 = kvidx[w * WSIZE + r0];
        int o1 = kvidx[w * WSIZE + r0 + 8];
        __half* base0 = &osc[(size_t)o0 * EMBED + h * HDIM];
        __half* base1 = &osc[(size_t)o1 * EMBED + h * HDIM];
        #pragma unroll
        for (int nt = 0; nt < 8; nt++) {
            int col = nt * 8 + 2 * l4;
            *reinterpret_cast<uint32_t*>(base0 + col) =
                packh2(Oacc[nt][0] * inv0, Oacc[nt][1] * inv0);
            *reinterpret_cast<uint32_t*>(base1 + col) =
                packh2(Oacc[nt][2] * inv1, Oacc[nt][3] * inv1);
        }
    }
}

// ---------------------------------------------------------------------------
extern "C" void kernel_launch(void* const* d_in, const int* in_sizes, int n_in,
                              void* d_out, int out_size)
{
    const float* x      = (const float*)d_in[0];
    const float* qkv_w  = (const float*)d_in[1];
    const float* qkv_b  = (const float*)d_in[2];
    const float* proj_w = (const float*)d_in[3];
    const float* proj_b = (const float*)d_in[4];
    const float* rope_c = (const float*)d_in[6];
    const float* rope_s = (const float*)d_in[7];
    const int*   kvi    = (const int*)d_in[8];
    float*       out    = (float*)d_out;

    __half *xh, *wqkv, *wproj, *qkvh, *osch;
    cudaGetSymbolAddress((void**)&xh,    g_xh);
    cudaGetSymbolAddress((void**)&wqkv,  g_wqkv);
    cudaGetSymbolAddress((void**)&wproj, g_wproj);
    cudaGetSymbolAddress((void**)&qkvh,  g_qkvh);
    cudaGetSymbolAddress((void**)&osch,  g_osch);

    // 0) fp32 -> fp16 conversions (x padded with zero row)
    {
        int nx_src = LTOT * EMBED, nx_tot = MTOT * EMBED;
        cvt_kernel<<<(nx_tot / 4 + 255) / 256, 256>>>(x, xh, nx_src, nx_tot);
        int nw = QKVN * EMBED;
        cvt_kernel<<<(nw / 4 + 255) / 256, 256>>>(qkv_w, wqkv, nw, nw);
        int np = EMBED * EMBED;
        cvt_kernel<<<(np / 4 + 255) / 256, 256>>>(proj_w, wproj, np, np);
    }

    cudaFuncSetAttribute(h16_gemm_kernel,
                         cudaFuncAttributeMaxDynamicSharedMemorySize, GEMM_SMEM_B);

    // 1) QKV GEMM with fused row gather (fp16 in, fp16 out)
    {
        dim3 grid(QKVN / 128, MTOT / 128);
        h16_gemm_kernel<<<grid, 256, GEMM_SMEM_B>>>(xh, wqkv, qkv_b, nullptr, qkvh,
                                                    kvi, MTOT, QKVN, EMBED);
    }

    // 2) fp16 tensor-core flash attention (RoPE + scatter fused)
    {
        cudaFuncSetAttribute(attn_tc_kernel,
                             cudaFuncAttributeMaxDynamicSharedMemorySize, ATTN_SMEM_B);
        dim3 grid(NWIN, NHEADS);
        attn_tc_kernel<<<grid, 512, ATTN_SMEM_B>>>(qkvh, rope_c, rope_s, kvi, osch);
    }

    // 3) Output projection (fp16 in, fp32 out)
    {
        dim3 grid(EMBED / 128, (LTOT + 127) / 128);
        h16_gemm_kernel<<<grid, 256, GEMM_SMEM_B>>>(osch, wproj, proj_b, out, nullptr,
                                                    nullptr, LTOT, EMBED, EMBED);
    }
}

// round 14
// speedup vs baseline: 1.3825x; 1.0773x over previous
#include <cuda_runtime.h>
#include <cuda_fp16.h>
#include <cstdint>
#include <cstddef>

#define EMBED    1024
#define NHEADS   16
#define HDIM     64
#define WSIZE    256
#define NWIN     64
#define MTOT     (NWIN*WSIZE)     /* 16384 */
#define LTOT     (MTOT-1)         /* 16383 */
#define QKVN     (3*EMBED)        /* 3072  */

// Scratch (allocation-free rule: __device__ globals)
__device__ __half g_xh[(size_t)MTOT * EMBED];    // x fp16, padding row zeroed
__device__ __half g_wqkv[(size_t)QKVN * EMBED];  // qkv_w fp16
__device__ __half g_wproj[(size_t)EMBED * EMBED];// proj_w fp16
__device__ __half g_qkvh[(size_t)MTOT * QKVN];   // gathered qkv fp16 (q,k ROPED)
__device__ __half g_osch[(size_t)MTOT * EMBED];  // scattered attention out fp16

__device__ __forceinline__ float ex2f(float x) {
    float y;
    asm("ex2.approx.f32 %0, %1;" : "=f"(y) : "f"(x));
    return y;
}
__device__ __forceinline__ uint32_t packh2(float lo, float hi) {
    __half2 h = __floats2half2_rn(lo, hi);
    return *reinterpret_cast<uint32_t*>(&h);
}
__device__ __forceinline__ void mma_f16(float* c, const uint32_t* a, const uint32_t* b) {
    asm volatile(
        "mma.sync.aligned.m16n8k16.row.col.f32.f16.f16.f32 "
        "{%0,%1,%2,%3}, {%4,%5,%6,%7}, {%8,%9}, {%0,%1,%2,%3};"
        : "+f"(c[0]), "+f"(c[1]), "+f"(c[2]), "+f"(c[3])
        : "r"(a[0]), "r"(a[1]), "r"(a[2]), "r"(a[3]), "r"(b[0]), "r"(b[1]));
}
__device__ __forceinline__ void ldsm_x4(uint32_t* r, uint32_t addr) {
    asm volatile("ldmatrix.sync.aligned.m8n8.x4.shared.b16 {%0,%1,%2,%3}, [%4];"
                 : "=r"(r[0]), "=r"(r[1]), "=r"(r[2]), "=r"(r[3]) : "r"(addr));
}
__device__ __forceinline__ void ldsm_x4_t(uint32_t* r, uint32_t addr) {
    asm volatile("ldmatrix.sync.aligned.m8n8.x4.trans.shared.b16 {%0,%1,%2,%3}, [%4];"
                 : "=r"(r[0]), "=r"(r[1]), "=r"(r[2]), "=r"(r[3]) : "r"(addr));
}
__device__ __forceinline__ uint32_t smem_u32(const void* p) {
    uint32_t a;
    asm("{ .reg .u64 t; cvta.to.shared.u64 t, %1; cvt.u32.u64 %0, t; }"
        : "=r"(a) : "l"(p));
    return a;
}
__device__ __forceinline__ void cp16(uint32_t smem, const void* g) {
    asm volatile("cp.async.cg.shared.global [%0], [%1], 16;" :: "r"(smem), "l"(g));
}
__device__ __forceinline__ void cp_commit() {
    asm volatile("cp.async.commit_group;" ::: "memory");
}
__device__ __forceinline__ void cp_wait1() {
    asm volatile("cp.async.wait_group 1;" ::: "memory");
}
__device__ __forceinline__ void cp_wait0() {
    asm volatile("cp.async.wait_group 0;" ::: "memory");
}

// ---------------------------------------------------------------------------
// fused fp32 -> fp16 conversion of x (zero-padded), qkv_w, proj_w — ONE launch
// ---------------------------------------------------------------------------
__global__ void cvt3_kernel(const float* __restrict__ s0, __half* __restrict__ d0,
                            int n0src, int n0tot,
                            const float* __restrict__ s1, __half* __restrict__ d1, int n1,
                            const float* __restrict__ s2, __half* __restrict__ d2, int n2)
{
    int i = (blockIdx.x * blockDim.x + threadIdx.x) << 2;
    const int t0 = n0tot, t1 = t0 + n1, t2 = t1 + n2;
    if (i >= t2) return;
    const float* src;
    __half* dst;
    int j;
    bool zero = false;
    if (i < t0)       { j = i;      src = s0; dst = d0; zero = (j >= n0src); }
    else if (i < t1)  { j = i - t0; src = s1; dst = d1; }
    else              { j = i - t1; src = s2; dst = d2; }
    uint2 u;
    if (!zero) {
        float4 v = *reinterpret_cast<const float4*>(src + j);
        u.x = packh2(v.x, v.y);
        u.y = packh2(v.z, v.w);
    } else {
        u = make_uint2(0u, 0u);
    }
    *reinterpret_cast<uint2*>(dst + j) = u;
}

// ---------------------------------------------------------------------------
// fp16 tensor-core GEMM (fp32 accum), cp.async 3-stage pipeline, BK=64.
// Optional fused RoPE epilogue: for output columns with type q/k (col<2048),
// rope pairs (d, d+32) live in the same thread as fragments (nt, nt+4).
// Bias added BEFORE rope (matches reference).
// ---------------------------------------------------------------------------
#define GSTR     72
#define TILE_HH  (128 * GSTR)
#define TILE_BB  (TILE_HH * 2)        /* 18432 bytes */
#define NSTAGE   3
#define GEMM_SMEM_B (2 * NSTAGE * TILE_BB)    /* 110592 B */

__global__ void __launch_bounds__(256, 2)
h16_gemm_kernel(const __half* __restrict__ A,
                const __half* __restrict__ B,
                const float* __restrict__ bias,
                float* __restrict__ Cf,
                __half* __restrict__ Ch,
                const int* __restrict__ gidx,
                const float* __restrict__ ropec,   // null = no rope
                const float* __restrict__ ropes,
                int Mrows, int N, int K)
{
    extern __shared__ __half smh[];
    __shared__ int arow[128];

    const int tid  = threadIdx.x;
    const int lane = tid & 31;
    const int wid  = tid >> 5;
    const int wm   = wid & 3;
    const int wn   = wid >> 2;
    const int bm   = blockIdx.y * 128;
    const int bn   = blockIdx.x * 128;

    if (tid < 128) {
        int m = bm + tid;
        arow[tid] = (m < Mrows) ? (gidx ? gidx[m] : m) : 0;
    }
    __syncthreads();

    const uint32_t smb   = smem_u32(smh);
    const uint32_t bsOff = NSTAGE * TILE_BB;

    const int crow = tid >> 3;
    const int ccol = (tid & 7) << 3;

    auto copy_tile = [&](int s, int k0) {
        uint32_t abase = smb + s * TILE_BB + ((crow * GSTR + ccol) << 1);
        uint32_t bbase = abase + bsOff;
        #pragma unroll
        for (int i = 0; i < 4; i++) {
            int row = crow + i * 32;
            uint32_t off = (uint32_t)(i * 32 * GSTR) << 1;
            cp16(abase + off, &A[(size_t)arow[row] * K + k0 + ccol]);
            cp16(bbase + off, &B[(size_t)(bn + row) * K + k0 + ccol]);
        }
        cp_commit();
    };

    float acc[2][8][4];
    #pragma unroll
    for (int mt = 0; mt < 2; mt++)
        #pragma unroll
        for (int nt = 0; nt < 8; nt++)
            #pragma unroll
            for (int i = 0; i < 4; i++) acc[mt][nt][i] = 0.f;

    const int g4 = lane >> 2;
    const int l4 = lane & 3;

    const uint32_t aL = smb +
        (((wm * 32 + (lane & 15)) * GSTR + ((lane >> 4) << 3)) << 1);
    const uint32_t bL = smb + bsOff +
        (((wn * 64 + (((lane >> 4) & 1) << 3) + (lane & 7)) * GSTR +
          (((lane >> 3) & 1) << 3)) << 1);
    const uint32_t MT16 = (16 * GSTR) << 1;

    const int T = K / 64;
    copy_tile(0, 0);
    if (T > 1) copy_tile(1, 64);

    for (int kt = 0; kt < T; kt++) {
        const int s = kt % NSTAGE;
        if (kt + 2 < T) cp_wait1(); else cp_wait0();
        __syncthreads();
        if (kt + 2 < T) copy_tile((kt + 2) % NSTAGE, (kt + 2) * 64);

        const uint32_t ab = aL + s * TILE_BB;
        const uint32_t bb = bL + s * TILE_BB;

        #pragma unroll
        for (int ks = 0; ks < 4; ks++) {
            uint32_t afr[2][4], bfr[16];
            ldsm_x4(afr[0], ab + ks * 32);
            ldsm_x4(afr[1], ab + MT16 + ks * 32);
            #pragma unroll
            for (int ntp = 0; ntp < 4; ntp++)
                ldsm_x4(&bfr[ntp * 4], bb + ntp * MT16 + ks * 32);
            #pragma unroll
            for (int mt = 0; mt < 2; mt++)
                #pragma unroll
                for (int nt = 0; nt < 8; nt++)
                    mma_f16(acc[mt][nt], afr[mt],
                            &bfr[((nt >> 1) << 2) + ((nt & 1) << 1)]);
        }
    }

    // ---- epilogue: bias, optional rope, store ----
    #pragma unroll
    for (int nt = 0; nt < 8; nt++) {
        int col = bn + wn * 64 + nt * 8 + l4 * 2;
        float b0 = bias[col], b1 = bias[col + 1];
        #pragma unroll
        for (int mt = 0; mt < 2; mt++) {
            acc[mt][nt][0] += b0; acc[mt][nt][1] += b1;
            acc[mt][nt][2] += b0; acc[mt][nt][3] += b1;
        }
    }

    if (ropec && bn < 2 * EMBED) {   // q/k column block: apply rope
        #pragma unroll
        for (int mt = 0; mt < 2; mt++) {
            int r0 = bm + wm * 32 + mt * 16 + g4;   // rows r0, r0+8 (< MTOT here)
            #pragma unroll
            for (int nt = 0; nt < 4; nt++) {
                int d = nt * 8 + l4 * 2;            // 0..30
                float2 c0 = *reinterpret_cast<const float2*>(&ropec[(size_t)r0 * HDIM + d]);
                float2 s0 = *reinterpret_cast<const float2*>(&ropes[(size_t)r0 * HDIM + d]);
                float2 c1 = *reinterpret_cast<const float2*>(&ropec[(size_t)(r0 + 8) * HDIM + d]);
                float2 s1 = *reinterpret_cast<const float2*>(&ropes[(size_t)(r0 + 8) * HDIM + d]);
                float lo, hi;
                lo = acc[mt][nt][0]; hi = acc[mt][nt + 4][0];
                acc[mt][nt][0]     = lo * c0.x - hi * s0.x;
                acc[mt][nt + 4][0] = hi * c0.x + lo * s0.x;
                lo = acc[mt][nt][1]; hi = acc[mt][nt + 4][1];
                acc[mt][nt][1]     = lo * c0.y - hi * s0.y;
                acc[mt][nt + 4][1] = hi * c0.y + lo * s0.y;
                lo = acc[mt][nt][2]; hi = acc[mt][nt + 4][2];
                acc[mt][nt][2]     = lo * c1.x - hi * s1.x;
                acc[mt][nt + 4][2] = hi * c1.x + lo * s1.x;
                lo = acc[mt][nt][3]; hi = acc[mt][nt + 4][3];
                acc[mt][nt][3]     = lo * c1.y - hi * s1.y;
                acc[mt][nt + 4][3] = hi * c1.y + lo * s1.y;
            }
        }
    }

    #pragma unroll
    for (int nt = 0; nt < 8; nt++) {
        int col = bn + wn * 64 + nt * 8 + l4 * 2;
        #pragma unroll
        for (int mt = 0; mt < 2; mt++) {
            int row = bm + wm * 32 + mt * 16 + g4;
            if (row < Mrows) {
                if (Ch)
                    *reinterpret_cast<uint32_t*>(&Ch[(size_t)row * N + col]) =
                        packh2(acc[mt][nt][0], acc[mt][nt][1]);
                else {
                    float2 v = make_float2(acc[mt][nt][0], acc[mt][nt][1]);
                    *reinterpret_cast<float2*>(&Cf[(size_t)row * N + col]) = v;
                }
            }
            if (row + 8 < Mrows) {
                if (Ch)
                    *reinterpret_cast<uint32_t*>(&Ch[(size_t)(row + 8) * N + col]) =
                        packh2(acc[mt][nt][2], acc[mt][nt][3]);
                else {
                    float2 v = make_float2(acc[mt][nt][2], acc[mt][nt][3]);
                    *reinterpret_cast<float2*>(&Cf[(size_t)(row + 8) * N + col]) = v;
                }
            }
        }
    }
}

// ---------------------------------------------------------------------------
// fp16 tensor-core flash attention; q/k arrive PRE-ROPED -> staging is pure
// cp.async copies. 512 threads (16 warps), warp = 16 Q rows.
// ---------------------------------------------------------------------------
#define AST   72
#define VS_H  (WSIZE * AST)
#define PB_H  (2 * WSIZE * AST)
#define ATTN_SMEM_B ((3 * WSIZE * AST) * 2)   /* 110592 bytes */

__global__ void __launch_bounds__(512)
attn_tc_kernel(const __half* __restrict__ qkv,
               const int* __restrict__ kvidx,
               __half* __restrict__ osc)
{
    extern __shared__ __half shh[];
    __half* Ksm = shh;
    __half* Vsm = shh + VS_H;
    __half* Pbm = shh + PB_H;

    const int w    = blockIdx.x;
    const int h    = blockIdx.y;
    const int tid  = threadIdx.x;
    const int lane = tid & 31;
    const int wid  = tid >> 5;
    const int g4   = lane >> 2;
    const int l4   = lane & 3;
    const int wrow = wid * 16;

    // ---- stage Q (Pb), K, V via cp.async; 2 threads per row, 32 halves each ----
    {
        const int row  = tid >> 1;
        const int half = (tid & 1) << 5;          // 0 or 32 halves
        const int gi   = w * WSIZE + row;
        const __half* base = &qkv[(size_t)gi * QKVN + h * HDIM + half];
        uint32_t pdst = smem_u32(Pbm + row * AST + half);
        uint32_t kdst = smem_u32(Ksm + row * AST + half);
        uint32_t vdst = smem_u32(Vsm + row * AST + half);
        #pragma unroll
        for (int i = 0; i < 4; i++) {
            cp16(pdst + i * 16, base + i * 8);                 // q
            cp16(kdst + i * 16, base + EMBED + i * 8);         // k
            cp16(vdst + i * 16, base + 2 * EMBED + i * 8);     // v
        }
        cp_commit();
    }
    cp_wait0();
    __syncthreads();

    const uint32_t ks_b = smem_u32(Ksm);
    const uint32_t vs_b = smem_u32(Vsm);
    const uint32_t pb_b = smem_u32(Pbm);
    const uint32_t ROWB = AST * 2;
    const uint32_t pbA = pb_b +
        (((wrow + (lane & 15)) * AST + ((lane >> 4) << 3)) << 1);
    const uint32_t ksB = ks_b +
        ((((((lane >> 4) & 1) << 3) + (lane & 7)) * AST +
          (((lane >> 3) & 1) << 3)) << 1);
    const uint32_t vsB = vs_b +
        ((((((lane >> 3) & 1) << 3) + (lane & 7)) * AST +
          (((lane >> 4) & 1) << 3)) << 1);

    uint32_t aQ[4][4];
    #pragma unroll
    for (int ks = 0; ks < 4; ks++)
        ldsm_x4(aQ[ks], pbA + ks * 32);
    __syncwarp();

    const float SC = 0.125f * 1.4426950408889634f;

    float mx[2] = {-1e30f, -1e30f}, lsum[2] = {0.f, 0.f};
    float Oacc[8][4];
    #pragma unroll
    for (int nt = 0; nt < 8; nt++)
        #pragma unroll
        for (int i = 0; i < 4; i++) Oacc[nt][i] = 0.f;

    for (int c = 0; c < 4; c++) {
        const int n0 = c * 64;

        float Sacc[8][4];
        #pragma unroll
        for (int nt = 0; nt < 8; nt++)
            #pragma unroll
            for (int i = 0; i < 4; i++) Sacc[nt][i] = 0.f;

        #pragma unroll
        for (int ks = 0; ks < 4; ks++) {
            uint32_t bf[16];
            #pragma unroll
            for (int ntp = 0; ntp < 4; ntp++)
                ldsm_x4(&bf[ntp * 4], ksB + (n0 + ntp * 16) * ROWB + ks * 32);
            #pragma unroll
            for (int nt = 0; nt < 8; nt++)
                mma_f16(Sacc[nt], aQ[ks],
                        &bf[((nt >> 1) << 2) + ((nt & 1) << 1)]);
        }

        #pragma unroll
        for (int hf = 0; hf < 2; hf++) {
            float rm = -1e30f;
            #pragma unroll
            for (int nt = 0; nt < 8; nt++) {
                rm = fmaxf(rm, Sacc[nt][2*hf]);
                rm = fmaxf(rm, Sacc[nt][2*hf+1]);
            }
            rm = fmaxf(rm, __shfl_xor_sync(0xffffffffu, rm, 1));
            rm = fmaxf(rm, __shfl_xor_sync(0xffffffffu, rm, 2));
            float nmx = fmaxf(mx[hf], rm * SC);
            float corr = ex2f(mx[hf] - nmx);
            mx[hf] = nmx;

            float ps = 0.f;
            #pragma unroll
            for (int nt = 0; nt < 8; nt++) {
                float p0 = ex2f(fmaf(Sacc[nt][2*hf],   SC, -nmx));
                float p1 = ex2f(fmaf(Sacc[nt][2*hf+1], SC, -nmx));
                ps += p0 + p1;
                Sacc[nt][2*hf]   = p0;
                Sacc[nt][2*hf+1] = p1;
            }
            ps += __shfl_xor_sync(0xffffffffu, ps, 1);
            ps += __shfl_xor_sync(0xffffffffu, ps, 2);
            lsum[hf] = lsum[hf] * corr + ps;

            #pragma unroll
            for (int nt = 0; nt < 8; nt++) {
                Oacc[nt][2*hf]   *= corr;
                Oacc[nt][2*hf+1] *= corr;
            }
        }

        {
            int r0 = wrow + g4;
            __half* p0r = Pbm + r0 * AST;
            __half* p1r = Pbm + (r0 + 8) * AST;
            #pragma unroll
            for (int nt = 0; nt < 8; nt++) {
                int col = nt * 8 + 2 * l4;
                *reinterpret_cast<uint32_t*>(p0r + col) = packh2(Sacc[nt][0], Sacc[nt][1]);
                *reinterpret_cast<uint32_t*>(p1r + col) = packh2(Sacc[nt][2], Sacc[nt][3]);
            }
        }
        __syncwarp();

        #pragma unroll
        for (int ks = 0; ks < 4; ks++) {
            uint32_t aP[4], bv[16];
            ldsm_x4(aP, pbA + ks * 32);
            #pragma unroll
            for (int ntp = 0; ntp < 4; ntp++)
                ldsm_x4_t(&bv[ntp * 4], vsB + (n0 + ks * 16) * ROWB + ntp * 32);
            #pragma unroll
            for (int nt = 0; nt < 8; nt++)
                mma_f16(Oacc[nt], aP,
                        &bv[((nt >> 1) << 2) + ((nt & 1) << 1)]);
        }
        __syncwarp();
    }

    {
        int r0 = wrow + g4;
        float inv0 = 1.f / lsum[0];
        float inv1 = 1.f / lsum[1];
        int o0 = kvidx[w * WSIZE + r0];
        int o1 = kvidx[w * WSIZE + r0 + 8];
        __half* base0 = &osc[(size_t)o0 * EMBED + h * HDIM];
        __half* base1 = &osc[(size_t)o1 * EMBED + h * HDIM];
        #pragma unroll
        for (int nt = 0; nt < 8; nt++) {
            int col = nt * 8 + 2 * l4;
            *reinterpret_cast<uint32_t*>(base0 + col) =
                packh2(Oacc[nt][0] * inv0, Oacc[nt][1] * inv0);
            *reinterpret_cast<uint32_t*>(base1 + col) =
                packh2(Oacc[nt][2] * inv1, Oacc[nt][3] * inv1);
        }
    }
}

// ---------------------------------------------------------------------------
extern "C" void kernel_launch(void* const* d_in, const int* in_sizes, int n_in,
                              void* d_out, int out_size)
{
    const float* x      = (const float*)d_in[0];
    const float* qkv_w  = (const float*)d_in[1];
    const float* qkv_b  = (const float*)d_in[2];
    const float* proj_w = (const float*)d_in[3];
    const float* proj_b = (const float*)d_in[4];
    const float* rope_c = (const float*)d_in[6];
    const float* rope_s = (const float*)d_in[7];
    const int*   kvi    = (const int*)d_in[8];
    float*       out    = (float*)d_out;

    __half *xh, *wqkv, *wproj, *qkvh, *osch;
    cudaGetSymbolAddress((void**)&xh,    g_xh);
    cudaGetSymbolAddress((void**)&wqkv,  g_wqkv);
    cudaGetSymbolAddress((void**)&wproj, g_wproj);
    cudaGetSymbolAddress((void**)&qkvh,  g_qkvh);
    cudaGetSymbolAddress((void**)&osch,  g_osch);

    // 0) fused fp32 -> fp16 conversions (one launch)
    {
        int nx_src = LTOT * EMBED, nx_tot = MTOT * EMBED;
        int nw = QKVN * EMBED, np = EMBED * EMBED;
        int total = nx_tot + nw + np;
        cvt3_kernel<<<(total / 4 + 255) / 256, 256>>>(
            x, xh, nx_src, nx_tot, qkv_w, wqkv, nw, proj_w, wproj, np);
    }

    cudaFuncSetAttribute(h16_gemm_kernel,
                         cudaFuncAttributeMaxDynamicSharedMemorySize, GEMM_SMEM_B);

    // 1) QKV GEMM, fused gather + bias + ROPE epilogue (fp16 out)
    {
        dim3 grid(QKVN / 128, MTOT / 128);
        h16_gemm_kernel<<<grid, 256, GEMM_SMEM_B>>>(xh, wqkv, qkv_b, nullptr, qkvh,
                                                    kvi, rope_c, rope_s,
                                                    MTOT, QKVN, EMBED);
    }

    // 2) fp16 flash attention (pre-roped q/k; scatter fused)
    {
        cudaFuncSetAttribute(attn_tc_kernel,
                             cudaFuncAttributeMaxDynamicSharedMemorySize, ATTN_SMEM_B);
        dim3 grid(NWIN, NHEADS);
        attn_tc_kernel<<<grid, 512, ATTN_SMEM_B>>>(qkvh, kvi, osch);
    }

    // 3) Output projection (fp16 in, fp32 out, no rope)
    {
        dim3 grid(EMBED / 128, (LTOT + 127) / 128);
        h16_gemm_kernel<<<grid, 256, GEMM_SMEM_B>>>(osch, wproj, proj_b, out, nullptr,
                                                    nullptr, nullptr, nullptr,
                                                    LTOT, EMBED, EMBED);
    }
}

// round 15
// speedup vs baseline: 1.4158x; 1.0240x over previous
#include <cuda_runtime.h>
#include <cuda_fp16.h>
#include <cstdint>
#include <cstddef>

#define EMBED    1024
#define NHEADS   16
#define HDIM     64
#define WSIZE    256
#define NWIN     64
#define MTOT     (NWIN*WSIZE)     /* 16384 */
#define LTOT     (MTOT-1)         /* 16383 */
#define QKVN     (3*EMBED)        /* 3072  */

// Scratch (allocation-free rule: __device__ globals)
__device__ __half g_xh[(size_t)MTOT * EMBED];    // x fp16, padding row zeroed
__device__ __half g_wqkv[(size_t)QKVN * EMBED];  // qkv_w fp16
__device__ __half g_wproj[(size_t)EMBED * EMBED];// proj_w fp16
__device__ __half g_qkvh[(size_t)MTOT * QKVN];   // gathered qkv fp16 (q,k ROPED)
__device__ __half g_osch[(size_t)MTOT * EMBED];  // scattered attention out fp16

__device__ __forceinline__ float ex2f(float x) {
    float y;
    asm("ex2.approx.f32 %0, %1;" : "=f"(y) : "f"(x));
    return y;
}
__device__ __forceinline__ uint32_t packh2(float lo, float hi) {
    __half2 h = __floats2half2_rn(lo, hi);
    return *reinterpret_cast<uint32_t*>(&h);
}
__device__ __forceinline__ void mma_f16(float* c, const uint32_t* a, const uint32_t* b) {
    asm volatile(
        "mma.sync.aligned.m16n8k16.row.col.f32.f16.f16.f32 "
        "{%0,%1,%2,%3}, {%4,%5,%6,%7}, {%8,%9}, {%0,%1,%2,%3};"
        : "+f"(c[0]), "+f"(c[1]), "+f"(c[2]), "+f"(c[3])
        : "r"(a[0]), "r"(a[1]), "r"(a[2]), "r"(a[3]), "r"(b[0]), "r"(b[1]));
}
__device__ __forceinline__ void ldsm_x4(uint32_t* r, uint32_t addr) {
    asm volatile("ldmatrix.sync.aligned.m8n8.x4.shared.b16 {%0,%1,%2,%3}, [%4];"
                 : "=r"(r[0]), "=r"(r[1]), "=r"(r[2]), "=r"(r[3]) : "r"(addr));
}
__device__ __forceinline__ void ldsm_x4_t(uint32_t* r, uint32_t addr) {
    asm volatile("ldmatrix.sync.aligned.m8n8.x4.trans.shared.b16 {%0,%1,%2,%3}, [%4];"
                 : "=r"(r[0]), "=r"(r[1]), "=r"(r[2]), "=r"(r[3]) : "r"(addr));
}
__device__ __forceinline__ uint32_t smem_u32(const void* p) {
    uint32_t a;
    asm("{ .reg .u64 t; cvta.to.shared.u64 t, %1; cvt.u32.u64 %0, t; }"
        : "=r"(a) : "l"(p));
    return a;
}
__device__ __forceinline__ void cp16(uint32_t smem, const void* g) {
    asm volatile("cp.async.cg.shared.global [%0], [%1], 16;" :: "r"(smem), "l"(g));
}
__device__ __forceinline__ void cp_commit() {
    asm volatile("cp.async.commit_group;" ::: "memory");
}
__device__ __forceinline__ void cp_wait1() {
    asm volatile("cp.async.wait_group 1;" ::: "memory");
}
__device__ __forceinline__ void cp_wait0() {
    asm volatile("cp.async.wait_group 0;" ::: "memory");
}

// ---------------------------------------------------------------------------
// fused fp32 -> fp16 conversion of x (zero-padded), qkv_w, proj_w — ONE launch
// ---------------------------------------------------------------------------
__global__ void cvt3_kernel(const float* __restrict__ s0, __half* __restrict__ d0,
                            int n0src, int n0tot,
                            const float* __restrict__ s1, __half* __restrict__ d1, int n1,
                            const float* __restrict__ s2, __half* __restrict__ d2, int n2)
{
    int i = (blockIdx.x * blockDim.x + threadIdx.x) << 2;
    const int t0 = n0tot, t1 = t0 + n1, t2 = t1 + n2;
    if (i >= t2) return;
    const float* src;
    __half* dst;
    int j;
    bool zero = false;
    if (i < t0)       { j = i;      src = s0; dst = d0; zero = (j >= n0src); }
    else if (i < t1)  { j = i - t0; src = s1; dst = d1; }
    else              { j = i - t1; src = s2; dst = d2; }
    uint2 u;
    if (!zero) {
        float4 v = *reinterpret_cast<const float4*>(src + j);
        u.x = packh2(v.x, v.y);
        u.y = packh2(v.z, v.w);
    } else {
        u = make_uint2(0u, 0u);
    }
    *reinterpret_cast<uint2*>(dst + j) = u;
}

// ---------------------------------------------------------------------------
// fp16 tensor-core GEMM (fp32 accum), cp.async 3-stage pipeline, BK=64.
//   BM=BN=128, 128 threads (4 warps, 2x2), warp tile 64x64.
//   2 blocks/SM co-resident (regs ~180 x 128, smem 110592 x 2 = 221 KB).
//   Optional fused RoPE epilogue for q/k columns (col < 2048).
// ---------------------------------------------------------------------------
#define GSTR     72
#define TILE_HH  (128 * GSTR)
#define TILE_BB  (TILE_HH * 2)        /* 18432 bytes */
#define NSTAGE   3
#define GEMM_SMEM_B (2 * NSTAGE * TILE_BB)    /* 110592 B */

__global__ void __launch_bounds__(128, 2)
h16_gemm_kernel(const __half* __restrict__ A,
                const __half* __restrict__ B,
                const float* __restrict__ bias,
                float* __restrict__ Cf,
                __half* __restrict__ Ch,
                const int* __restrict__ gidx,
                const float* __restrict__ ropec,   // null = no rope
                const float* __restrict__ ropes,
                int Mrows, int N, int K)
{
    extern __shared__ __half smh[];
    __shared__ int arow[128];

    const int tid  = threadIdx.x;
    const int lane = tid & 31;
    const int wid  = tid >> 5;        // 0..3
    const int wm   = wid & 1;         // 2 warp rows (64 each)
    const int wn   = wid >> 1;        // 2 warp cols (64 each)
    const int bm   = blockIdx.y * 128;
    const int bn   = blockIdx.x * 128;

    if (tid < 128) {
        int m = bm + tid;
        arow[tid] = (m < Mrows) ? (gidx ? gidx[m] : m) : 0;
    }
    __syncthreads();

    const uint32_t smb   = smem_u32(smh);
    const uint32_t bsOff = NSTAGE * TILE_BB;

    // copy mapping: 1024 16B-chunks per tile, 128 threads -> 8 chunks each
    const int crow = tid >> 3;            // 0..15 (+16 per pass, 8 passes)
    const int ccol = (tid & 7) << 3;      // halves 0..56

    auto copy_tile = [&](int s, int k0) {
        uint32_t abase = smb + s * TILE_BB + ((crow * GSTR + ccol) << 1);
        uint32_t bbase = abase + bsOff;
        #pragma unroll
        for (int i = 0; i < 8; i++) {
            int row = crow + i * 16;
            uint32_t off = (uint32_t)(i * 16 * GSTR) << 1;
            cp16(abase + off, &A[(size_t)arow[row] * K + k0 + ccol]);
            cp16(bbase + off, &B[(size_t)(bn + row) * K + k0 + ccol]);
        }
        cp_commit();
    };

    float acc[4][8][4];
    #pragma unroll
    for (int mt = 0; mt < 4; mt++)
        #pragma unroll
        for (int nt = 0; nt < 8; nt++)
            #pragma unroll
            for (int i = 0; i < 4; i++) acc[mt][nt][i] = 0.f;

    const int g4 = lane >> 2;
    const int l4 = lane & 3;

    const uint32_t aL = smb +
        (((wm * 64 + (lane & 15)) * GSTR + ((lane >> 4) << 3)) << 1);
    const uint32_t bL = smb + bsOff +
        (((wn * 64 + (((lane >> 4) & 1) << 3) + (lane & 7)) * GSTR +
          (((lane >> 3) & 1) << 3)) << 1);
    const uint32_t MT16 = (16 * GSTR) << 1;

    const int T = K / 64;
    copy_tile(0, 0);
    if (T > 1) copy_tile(1, 64);

    for (int kt = 0; kt < T; kt++) {
        const int s = kt % NSTAGE;
        if (kt + 2 < T) cp_wait1(); else cp_wait0();
        __syncthreads();
        if (kt + 2 < T) copy_tile((kt + 2) % NSTAGE, (kt + 2) * 64);

        const uint32_t ab = aL + s * TILE_BB;
        const uint32_t bb = bL + s * TILE_BB;

        #pragma unroll
        for (int ks = 0; ks < 4; ks++) {
            uint32_t afr[4][4], bfr[16];
            #pragma unroll
            for (int mt = 0; mt < 4; mt++)
                ldsm_x4(afr[mt], ab + mt * MT16 + ks * 32);
            #pragma unroll
            for (int ntp = 0; ntp < 4; ntp++)
                ldsm_x4(&bfr[ntp * 4], bb + ntp * MT16 + ks * 32);
            #pragma unroll
            for (int mt = 0; mt < 4; mt++)
                #pragma unroll
                for (int nt = 0; nt < 8; nt++)
                    mma_f16(acc[mt][nt], afr[mt],
                            &bfr[((nt >> 1) << 2) + ((nt & 1) << 1)]);
        }
    }

    // ---- epilogue: bias, optional rope, store ----
    #pragma unroll
    for (int nt = 0; nt < 8; nt++) {
        int col = bn + wn * 64 + nt * 8 + l4 * 2;
        float b0 = bias[col], b1 = bias[col + 1];
        #pragma unroll
        for (int mt = 0; mt < 4; mt++) {
            acc[mt][nt][0] += b0; acc[mt][nt][1] += b1;
            acc[mt][nt][2] += b0; acc[mt][nt][3] += b1;
        }
    }

    if (ropec && bn < 2 * EMBED) {   // q/k column block: apply rope
        #pragma unroll
        for (int mt = 0; mt < 4; mt++) {
            int r0 = bm + wm * 64 + mt * 16 + g4;
            #pragma unroll
            for (int nt = 0; nt < 4; nt++) {
                int d = nt * 8 + l4 * 2;            // 0..30
                float2 c0 = *reinterpret_cast<const float2*>(&ropec[(size_t)r0 * HDIM + d]);
                float2 s0 = *reinterpret_cast<const float2*>(&ropes[(size_t)r0 * HDIM + d]);
                float2 c1 = *reinterpret_cast<const float2*>(&ropec[(size_t)(r0 + 8) * HDIM + d]);
                float2 s1 = *reinterpret_cast<const float2*>(&ropes[(size_t)(r0 + 8) * HDIM + d]);
                float lo, hi;
                lo = acc[mt][nt][0]; hi = acc[mt][nt + 4][0];
                acc[mt][nt][0]     = lo * c0.x - hi * s0.x;
                acc[mt][nt + 4][0] = hi * c0.x + lo * s0.x;
                lo = acc[mt][nt][1]; hi = acc[mt][nt + 4][1];
                acc[mt][nt][1]     = lo * c0.y - hi * s0.y;
                acc[mt][nt + 4][1] = hi * c0.y + lo * s0.y;
                lo = acc[mt][nt][2]; hi = acc[mt][nt + 4][2];
                acc[mt][nt][2]     = lo * c1.x - hi * s1.x;
                acc[mt][nt + 4][2] = hi * c1.x + lo * s1.x;
                lo = acc[mt][nt][3]; hi = acc[mt][nt + 4][3];
                acc[mt][nt][3]     = lo * c1.y - hi * s1.y;
                acc[mt][nt + 4][3] = hi * c1.y + lo * s1.y;
            }
        }
    }

    #pragma unroll
    for (int nt = 0; nt < 8; nt++) {
        int col = bn + wn * 64 + nt * 8 + l4 * 2;
        #pragma unroll
        for (int mt = 0; mt < 4; mt++) {
            int row = bm + wm * 64 + mt * 16 + g4;
            if (row < Mrows) {
                if (Ch)
                    *reinterpret_cast<uint32_t*>(&Ch[(size_t)row * N + col]) =
                        packh2(acc[mt][nt][0], acc[mt][nt][1]);
                else {
                    float2 v = make_float2(acc[mt][nt][0], acc[mt][nt][1]);
                    *reinterpret_cast<float2*>(&Cf[(size_t)row * N + col]) = v;
                }
            }
            if (row + 8 < Mrows) {
                if (Ch)
                    *reinterpret_cast<uint32_t*>(&Ch[(size_t)(row + 8) * N + col]) =
                        packh2(acc[mt][nt][2], acc[mt][nt][3]);
                else {
                    float2 v = make_float2(acc[mt][nt][2], acc[mt][nt][3]);
                    *reinterpret_cast<float2*>(&Cf[(size_t)(row + 8) * N + col]) = v;
                }
            }
        }
    }
}

// ---------------------------------------------------------------------------
// fp16 tensor-core flash attention; q/k arrive PRE-ROPED -> staging is pure
// cp.async copies. 512 threads (16 warps), warp = 16 Q rows. (unchanged R14)
// ---------------------------------------------------------------------------
#define AST   72
#define VS_H  (WSIZE * AST)
#define PB_H  (2 * WSIZE * AST)
#define ATTN_SMEM_B ((3 * WSIZE * AST) * 2)   /* 110592 bytes */

__global__ void __launch_bounds__(512)
attn_tc_kernel(const __half* __restrict__ qkv,
               const int* __restrict__ kvidx,
               __half* __restrict__ osc)
{
    extern __shared__ __half shh[];
    __half* Ksm = shh;
    __half* Vsm = shh + VS_H;
    __half* Pbm = shh + PB_H;

    const int w    = blockIdx.x;
    const int h    = blockIdx.y;
    const int tid  = threadIdx.x;
    const int lane = tid & 31;
    const int wid  = tid >> 5;
    const int g4   = lane >> 2;
    const int l4   = lane & 3;
    const int wrow = wid * 16;

    {
        const int row  = tid >> 1;
        const int half = (tid & 1) << 5;
        const int gi   = w * WSIZE + row;
        const __half* base = &qkv[(size_t)gi * QKVN + h * HDIM + half];
        uint32_t pdst = smem_u32(Pbm + row * AST + half);
        uint32_t kdst = smem_u32(Ksm + row * AST + half);
        uint32_t vdst = smem_u32(Vsm + row * AST + half);
        #pragma unroll
        for (int i = 0; i < 4; i++) {
            cp16(pdst + i * 16, base + i * 8);
            cp16(kdst + i * 16, base + EMBED + i * 8);
            cp16(vdst + i * 16, base + 2 * EMBED + i * 8);
        }
        cp_commit();
    }
    cp_wait0();
    __syncthreads();

    const uint32_t ks_b = smem_u32(Ksm);
    const uint32_t vs_b = smem_u32(Vsm);
    const uint32_t pb_b = smem_u32(Pbm);
    const uint32_t ROWB = AST * 2;
    const uint32_t pbA = pb_b +
        (((wrow + (lane & 15)) * AST + ((lane >> 4) << 3)) << 1);
    const uint32_t ksB = ks_b +
        ((((((lane >> 4) & 1) << 3) + (lane & 7)) * AST +
          (((lane >> 3) & 1) << 3)) << 1);
    const uint32_t vsB = vs_b +
        ((((((lane >> 3) & 1) << 3) + (lane & 7)) * AST +
          (((lane >> 4) & 1) << 3)) << 1);

    uint32_t aQ[4][4];
    #pragma unroll
    for (int ks = 0; ks < 4; ks++)
        ldsm_x4(aQ[ks], pbA + ks * 32);
    __syncwarp();

    const float SC = 0.125f * 1.4426950408889634f;

    float mx[2] = {-1e30f, -1e30f}, lsum[2] = {0.f, 0.f};
    float Oacc[8][4];
    #pragma unroll
    for (int nt = 0; nt < 8; nt++)
        #pragma unroll
        for (int i = 0; i < 4; i++) Oacc[nt][i] = 0.f;

    for (int c = 0; c < 4; c++) {
        const int n0 = c * 64;

        float Sacc[8][4];
        #pragma unroll
        for (int nt = 0; nt < 8; nt++)
            #pragma unroll
            for (int i = 0; i < 4; i++) Sacc[nt][i] = 0.f;

        #pragma unroll
        for (int ks = 0; ks < 4; ks++) {
            uint32_t bf[16];
            #pragma unroll
            for (int ntp = 0; ntp < 4; ntp++)
                ldsm_x4(&bf[ntp * 4], ksB + (n0 + ntp * 16) * ROWB + ks * 32);
            #pragma unroll
            for (int nt = 0; nt < 8; nt++)
                mma_f16(Sacc[nt], aQ[ks],
                        &bf[((nt >> 1) << 2) + ((nt & 1) << 1)]);
        }

        #pragma unroll
        for (int hf = 0; hf < 2; hf++) {
            float rm = -1e30f;
            #pragma unroll
            for (int nt = 0; nt < 8; nt++) {
                rm = fmaxf(rm, Sacc[nt][2*hf]);
                rm = fmaxf(rm, Sacc[nt][2*hf+1]);
            }
            rm = fmaxf(rm, __shfl_xor_sync(0xffffffffu, rm, 1));
            rm = fmaxf(rm, __shfl_xor_sync(0xffffffffu, rm, 2));
            float nmx = fmaxf(mx[hf], rm * SC);
            float corr = ex2f(mx[hf] - nmx);
            mx[hf] = nmx;

            float ps = 0.f;
            #pragma unroll
            for (int nt = 0; nt < 8; nt++) {
                float p0 = ex2f(fmaf(Sacc[nt][2*hf],   SC, -nmx));
                float p1 = ex2f(fmaf(Sacc[nt][2*hf+1], SC, -nmx));
                ps += p0 + p1;
                Sacc[nt][2*hf]   = p0;
                Sacc[nt][2*hf+1] = p1;
            }
            ps += __shfl_xor_sync(0xffffffffu, ps, 1);
            ps += __shfl_xor_sync(0xffffffffu, ps, 2);
            lsum[hf] = lsum[hf] * corr + ps;

            #pragma unroll
            for (int nt = 0; nt < 8; nt++) {
                Oacc[nt][2*hf]   *= corr;
                Oacc[nt][2*hf+1] *= corr;
            }
        }

        {
            int r0 = wrow + g4;
            __half* p0r = Pbm + r0 * AST;
            __half* p1r = Pbm + (r0 + 8) * AST;
            #pragma unroll
            for (int nt = 0; nt < 8; nt++) {
                int col = nt * 8 + 2 * l4;
                *reinterpret_cast<uint32_t*>(p0r + col) = packh2(Sacc[nt][0], Sacc[nt][1]);
                *reinterpret_cast<uint32_t*>(p1r + col) = packh2(Sacc[nt][2], Sacc[nt][3]);
            }
        }
        __syncwarp();

        #pragma unroll
        for (int ks = 0; ks < 4; ks++) {
            uint32_t aP[4], bv[16];
            ldsm_x4(aP, pbA + ks * 32);
            #pragma unroll
            for (int ntp = 0; ntp < 4; ntp++)
                ldsm_x4_t(&bv[ntp * 4], vsB + (n0 + ks * 16) * ROWB + ntp * 32);
            #pragma unroll
            for (int nt = 0; nt < 8; nt++)
                mma_f16(Oacc[nt], aP,
                        &bv[((nt >> 1) << 2) + ((nt & 1) << 1)]);
        }
        __syncwarp();
    }

    {
        int r0 = wrow + g4;
        float inv0 = 1.f / lsum[0];
        float inv1 = 1.f / lsum[1];
        int o0 = kvidx[w * WSIZE + r0];
        int o1 = kvidx[w * WSIZE + r0 + 8];
        __half* base0 = &osc[(size_t)o0 * EMBED + h * HDIM];
        __half* base1 = &osc[(size_t)o1 * EMBED + h * HDIM];
        #pragma unroll
        for (int nt = 0; nt < 8; nt++) {
            int col = nt * 8 + 2 * l4;
            *reinterpret_cast<uint32_t*>(base0 + col) =
                packh2(Oacc[nt][0] * inv0, Oacc[nt][1] * inv0);
            *reinterpret_cast<uint32_t*>(base1 + col) =
                packh2(Oacc[nt][2] * inv1, Oacc[nt][3] * inv1);
        }
    }
}

// ---------------------------------------------------------------------------
extern "C" void kernel_launch(void* const* d_in, const int* in_sizes, int n_in,
                              void* d_out, int out_size)
{
    const float* x      = (const float*)d_in[0];
    const float* qkv_w  = (const float*)d_in[1];
    const float* qkv_b  = (const float*)d_in[2];
    const float* proj_w = (const float*)d_in[3];
    const float* proj_b = (const float*)d_in[4];
    const float* rope_c = (const float*)d_in[6];
    const float* rope_s = (const float*)d_in[7];
    const int*   kvi    = (const int*)d_in[8];
    float*       out    = (float*)d_out;

    __half *xh, *wqkv, *wproj, *qkvh, *osch;
    cudaGetSymbolAddress((void**)&xh,    g_xh);
    cudaGetSymbolAddress((void**)&wqkv,  g_wqkv);
    cudaGetSymbolAddress((void**)&wproj, g_wproj);
    cudaGetSymbolAddress((void**)&qkvh,  g_qkvh);
    cudaGetSymbolAddress((void**)&osch,  g_osch);

    // 0) fused fp32 -> fp16 conversions (one launch)
    {
        int nx_src = LTOT * EMBED, nx_tot = MTOT * EMBED;
        int nw = QKVN * EMBED, np = EMBED * EMBED;
        int total = nx_tot + nw + np;
        cvt3_kernel<<<(total / 4 + 255) / 256, 256>>>(
            x, xh, nx_src, nx_tot, qkv_w, wqkv, nw, proj_w, wproj, np);
    }

    cudaFuncSetAttribute(h16_gemm_kernel,
                         cudaFuncAttributeMaxDynamicSharedMemorySize, GEMM_SMEM_B);

    // 1) QKV GEMM, fused gather + bias + ROPE epilogue (fp16 out)
    {
        dim3 grid(QKVN / 128, MTOT / 128);
        h16_gemm_kernel<<<grid, 128, GEMM_SMEM_B>>>(xh, wqkv, qkv_b, nullptr, qkvh,
                                                    kvi, rope_c, rope_s,
                                                    MTOT, QKVN, EMBED);
    }

    // 2) fp16 flash attention (pre-roped q/k; scatter fused)
    {
        cudaFuncSetAttribute(attn_tc_kernel,
                             cudaFuncAttributeMaxDynamicSharedMemorySize, ATTN_SMEM_B);
        dim3 grid(NWIN, NHEADS);
        attn_tc_kernel<<<grid, 512, ATTN_SMEM_B>>>(qkvh, kvi, osch);
    }

    // 3) Output projection (fp16 in, fp32 out, no rope)
    {
        dim3 grid(EMBED / 128, (LTOT + 127) / 128);
        h16_gemm_kernel<<<grid, 128, GEMM_SMEM_B>>>(osch, wproj, proj_b, out, nullptr,
                                                    nullptr, nullptr, nullptr,
                                                    LTOT, EMBED, EMBED);
    }
}

// round 16
// speedup vs baseline: 1.4260x; 1.0073x over previous
#include <cuda_runtime.h>
#include <cuda_fp16.h>
#include <cstdint>
#include <cstddef>

#define EMBED    1024
#define NHEADS   16
#define HDIM     64
#define WSIZE    256
#define NWIN     64
#define MTOT     (NWIN*WSIZE)     /* 16384 */
#define LTOT     (MTOT-1)         /* 16383 */
#define QKVN     (3*EMBED)        /* 3072  */

// Scratch (allocation-free rule: __device__ globals)
__device__ __half g_xh[(size_t)MTOT * EMBED];    // x fp16, padding row zeroed
__device__ __half g_wqkv[(size_t)QKVN * EMBED];  // qkv_w fp16
__device__ __half g_wproj[(size_t)EMBED * EMBED];// proj_w fp16
__device__ __half g_qkvh[(size_t)MTOT * QKVN];   // gathered qkv fp16 (q,k ROPED)
__device__ __half g_osch[(size_t)MTOT * EMBED];  // scattered attention out fp16

__device__ __forceinline__ float ex2f(float x) {
    float y;
    asm("ex2.approx.f32 %0, %1;" : "=f"(y) : "f"(x));
    return y;
}
__device__ __forceinline__ uint32_t packh2(float lo, float hi) {
    __half2 h = __floats2half2_rn(lo, hi);
    return *reinterpret_cast<uint32_t*>(&h);
}
__device__ __forceinline__ void mma_f16(float* c, const uint32_t* a, const uint32_t* b) {
    asm volatile(
        "mma.sync.aligned.m16n8k16.row.col.f32.f16.f16.f32 "
        "{%0,%1,%2,%3}, {%4,%5,%6,%7}, {%8,%9}, {%0,%1,%2,%3};"
        : "+f"(c[0]), "+f"(c[1]), "+f"(c[2]), "+f"(c[3])
        : "r"(a[0]), "r"(a[1]), "r"(a[2]), "r"(a[3]), "r"(b[0]), "r"(b[1]));
}
__device__ __forceinline__ void ldsm_x4(uint32_t* r, uint32_t addr) {
    asm volatile("ldmatrix.sync.aligned.m8n8.x4.shared.b16 {%0,%1,%2,%3}, [%4];"
                 : "=r"(r[0]), "=r"(r[1]), "=r"(r[2]), "=r"(r[3]) : "r"(addr));
}
__device__ __forceinline__ void ldsm_x4_t(uint32_t* r, uint32_t addr) {
    asm volatile("ldmatrix.sync.aligned.m8n8.x4.trans.shared.b16 {%0,%1,%2,%3}, [%4];"
                 : "=r"(r[0]), "=r"(r[1]), "=r"(r[2]), "=r"(r[3]) : "r"(addr));
}
__device__ __forceinline__ uint32_t smem_u32(const void* p) {
    uint32_t a;
    asm("{ .reg .u64 t; cvta.to.shared.u64 t, %1; cvt.u32.u64 %0, t; }"
        : "=r"(a) : "l"(p));
    return a;
}
__device__ __forceinline__ void cp16(uint32_t smem, const void* g) {
    asm volatile("cp.async.cg.shared.global [%0], [%1], 16;" :: "r"(smem), "l"(g));
}
__device__ __forceinline__ void cp_commit() {
    asm volatile("cp.async.commit_group;" ::: "memory");
}
__device__ __forceinline__ void cp_wait1() {
    asm volatile("cp.async.wait_group 1;" ::: "memory");
}
__device__ __forceinline__ void cp_wait0() {
    asm volatile("cp.async.wait_group 0;" ::: "memory");
}

// ---------------------------------------------------------------------------
// fused fp32 -> fp16 conversion of x (zero-padded), qkv_w, proj_w — ONE launch
// ---------------------------------------------------------------------------
__global__ void cvt3_kernel(const float* __restrict__ s0, __half* __restrict__ d0,
                            int n0src, int n0tot,
                            const float* __restrict__ s1, __half* __restrict__ d1, int n1,
                            const float* __restrict__ s2, __half* __restrict__ d2, int n2)
{
    int i = (blockIdx.x * blockDim.x + threadIdx.x) << 2;
    const int t0 = n0tot, t1 = t0 + n1, t2 = t1 + n2;
    if (i >= t2) return;
    const float* src;
    __half* dst;
    int j;
    bool zero = false;
    if (i < t0)       { j = i;      src = s0; dst = d0; zero = (j >= n0src); }
    else if (i < t1)  { j = i - t0; src = s1; dst = d1; }
    else              { j = i - t1; src = s2; dst = d2; }
    uint2 u;
    if (!zero) {
        float4 v = *reinterpret_cast<const float4*>(src + j);
        u.x = packh2(v.x, v.y);
        u.y = packh2(v.z, v.w);
    } else {
        u = make_uint2(0u, 0u);
    }
    *reinterpret_cast<uint2*>(dst + j) = u;
}

// ---------------------------------------------------------------------------
// fp16 tensor-core GEMM (fp32 accum), cp.async 3-stage pipeline, BK=64.
//   BM=BN=128, 128 threads (4 warps, 2x2), warp tile 64x64.  (unchanged R15)
// ---------------------------------------------------------------------------
#define GSTR     72
#define TILE_HH  (128 * GSTR)
#define TILE_BB  (TILE_HH * 2)        /* 18432 bytes */
#define NSTAGE   3
#define GEMM_SMEM_B (2 * NSTAGE * TILE_BB)    /* 110592 B */

__global__ void __launch_bounds__(128, 2)
h16_gemm_kernel(const __half* __restrict__ A,
                const __half* __restrict__ B,
                const float* __restrict__ bias,
                float* __restrict__ Cf,
                __half* __restrict__ Ch,
                const int* __restrict__ gidx,
                const float* __restrict__ ropec,   // null = no rope
                const float* __restrict__ ropes,
                int Mrows, int N, int K)
{
    extern __shared__ __half smh[];
    __shared__ int arow[128];

    const int tid  = threadIdx.x;
    const int lane = tid & 31;
    const int wid  = tid >> 5;        // 0..3
    const int wm   = wid & 1;
    const int wn   = wid >> 1;
    const int bm   = blockIdx.y * 128;
    const int bn   = blockIdx.x * 128;

    if (tid < 128) {
        int m = bm + tid;
        arow[tid] = (m < Mrows) ? (gidx ? gidx[m] : m) : 0;
    }
    __syncthreads();

    const uint32_t smb   = smem_u32(smh);
    const uint32_t bsOff = NSTAGE * TILE_BB;

    const int crow = tid >> 3;
    const int ccol = (tid & 7) << 3;

    auto copy_tile = [&](int s, int k0) {
        uint32_t abase = smb + s * TILE_BB + ((crow * GSTR + ccol) << 1);
        uint32_t bbase = abase + bsOff;
        #pragma unroll
        for (int i = 0; i < 8; i++) {
            int row = crow + i * 16;
            uint32_t off = (uint32_t)(i * 16 * GSTR) << 1;
            cp16(abase + off, &A[(size_t)arow[row] * K + k0 + ccol]);
            cp16(bbase + off, &B[(size_t)(bn + row) * K + k0 + ccol]);
        }
        cp_commit();
    };

    float acc[4][8][4];
    #pragma unroll
    for (int mt = 0; mt < 4; mt++)
        #pragma unroll
        for (int nt = 0; nt < 8; nt++)
            #pragma unroll
            for (int i = 0; i < 4; i++) acc[mt][nt][i] = 0.f;

    const int g4 = lane >> 2;
    const int l4 = lane & 3;

    const uint32_t aL = smb +
        (((wm * 64 + (lane & 15)) * GSTR + ((lane >> 4) << 3)) << 1);
    const uint32_t bL = smb + bsOff +
        (((wn * 64 + (((lane >> 4) & 1) << 3) + (lane & 7)) * GSTR +
          (((lane >> 3) & 1) << 3)) << 1);
    const uint32_t MT16 = (16 * GSTR) << 1;

    const int T = K / 64;
    copy_tile(0, 0);
    if (T > 1) copy_tile(1, 64);

    for (int kt = 0; kt < T; kt++) {
        const int s = kt % NSTAGE;
        if (kt + 2 < T) cp_wait1(); else cp_wait0();
        __syncthreads();
        if (kt + 2 < T) copy_tile((kt + 2) % NSTAGE, (kt + 2) * 64);

        const uint32_t ab = aL + s * TILE_BB;
        const uint32_t bb = bL + s * TILE_BB;

        #pragma unroll
        for (int ks = 0; ks < 4; ks++) {
            uint32_t afr[4][4], bfr[16];
            #pragma unroll
            for (int mt = 0; mt < 4; mt++)
                ldsm_x4(afr[mt], ab + mt * MT16 + ks * 32);
            #pragma unroll
            for (int ntp = 0; ntp < 4; ntp++)
                ldsm_x4(&bfr[ntp * 4], bb + ntp * MT16 + ks * 32);
            #pragma unroll
            for (int mt = 0; mt < 4; mt++)
                #pragma unroll
                for (int nt = 0; nt < 8; nt++)
                    mma_f16(acc[mt][nt], afr[mt],
                            &bfr[((nt >> 1) << 2) + ((nt & 1) << 1)]);
        }
    }

    // ---- epilogue: bias, optional rope, store ----
    #pragma unroll
    for (int nt = 0; nt < 8; nt++) {
        int col = bn + wn * 64 + nt * 8 + l4 * 2;
        float b0 = bias[col], b1 = bias[col + 1];
        #pragma unroll
        for (int mt = 0; mt < 4; mt++) {
            acc[mt][nt][0] += b0; acc[mt][nt][1] += b1;
            acc[mt][nt][2] += b0; acc[mt][nt][3] += b1;
        }
    }

    if (ropec && bn < 2 * EMBED) {
        #pragma unroll
        for (int mt = 0; mt < 4; mt++) {
            int r0 = bm + wm * 64 + mt * 16 + g4;
            #pragma unroll
            for (int nt = 0; nt < 4; nt++) {
                int d = nt * 8 + l4 * 2;
                float2 c0 = *reinterpret_cast<const float2*>(&ropec[(size_t)r0 * HDIM + d]);
                float2 s0 = *reinterpret_cast<const float2*>(&ropes[(size_t)r0 * HDIM + d]);
                float2 c1 = *reinterpret_cast<const float2*>(&ropec[(size_t)(r0 + 8) * HDIM + d]);
                float2 s1 = *reinterpret_cast<const float2*>(&ropes[(size_t)(r0 + 8) * HDIM + d]);
                float lo, hi;
                lo = acc[mt][nt][0]; hi = acc[mt][nt + 4][0];
                acc[mt][nt][0]     = lo * c0.x - hi * s0.x;
                acc[mt][nt + 4][0] = hi * c0.x + lo * s0.x;
                lo = acc[mt][nt][1]; hi = acc[mt][nt + 4][1];
                acc[mt][nt][1]     = lo * c0.y - hi * s0.y;
                acc[mt][nt + 4][1] = hi * c0.y + lo * s0.y;
                lo = acc[mt][nt][2]; hi = acc[mt][nt + 4][2];
                acc[mt][nt][2]     = lo * c1.x - hi * s1.x;
                acc[mt][nt + 4][2] = hi * c1.x + lo * s1.x;
                lo = acc[mt][nt][3]; hi = acc[mt][nt + 4][3];
                acc[mt][nt][3]     = lo * c1.y - hi * s1.y;
                acc[mt][nt + 4][3] = hi * c1.y + lo * s1.y;
            }
        }
    }

    #pragma unroll
    for (int nt = 0; nt < 8; nt++) {
        int col = bn + wn * 64 + nt * 8 + l4 * 2;
        #pragma unroll
        for (int mt = 0; mt < 4; mt++) {
            int row = bm + wm * 64 + mt * 16 + g4;
            if (row < Mrows) {
                if (Ch)
                    *reinterpret_cast<uint32_t*>(&Ch[(size_t)row * N + col]) =
                        packh2(acc[mt][nt][0], acc[mt][nt][1]);
                else {
                    float2 v = make_float2(acc[mt][nt][0], acc[mt][nt][1]);
                    *reinterpret_cast<float2*>(&Cf[(size_t)row * N + col]) = v;
                }
            }
            if (row + 8 < Mrows) {
                if (Ch)
                    *reinterpret_cast<uint32_t*>(&Ch[(size_t)(row + 8) * N + col]) =
                        packh2(acc[mt][nt][2], acc[mt][nt][3]);
                else {
                    float2 v = make_float2(acc[mt][nt][2], acc[mt][nt][3]);
                    *reinterpret_cast<float2*>(&Cf[(size_t)(row + 8) * N + col]) = v;
                }
            }
        }
    }
}

// ---------------------------------------------------------------------------
// fp16 flash attention; P fragments built directly from S accumulators
// (mma C-layout == next mma's A-layout when n becomes k). No P smem trip.
// ---------------------------------------------------------------------------
#define AST   72
#define VS_H  (WSIZE * AST)
#define PB_H  (2 * WSIZE * AST)
#define ATTN_SMEM_B ((3 * WSIZE * AST) * 2)   /* 110592 bytes */

__global__ void __launch_bounds__(512)
attn_tc_kernel(const __half* __restrict__ qkv,
               const int* __restrict__ kvidx,
               __half* __restrict__ osc)
{
    extern __shared__ __half shh[];
    __half* Ksm = shh;
    __half* Vsm = shh + VS_H;
    __half* Pbm = shh + PB_H;     // Q staging only

    const int w    = blockIdx.x;
    const int h    = blockIdx.y;
    const int tid  = threadIdx.x;
    const int lane = tid & 31;
    const int wid  = tid >> 5;
    const int g4   = lane >> 2;
    const int l4   = lane & 3;
    const int wrow = wid * 16;

    {
        const int row  = tid >> 1;
        const int half = (tid & 1) << 5;
        const int gi   = w * WSIZE + row;
        const __half* base = &qkv[(size_t)gi * QKVN + h * HDIM + half];
        uint32_t pdst = smem_u32(Pbm + row * AST + half);
        uint32_t kdst = smem_u32(Ksm + row * AST + half);
        uint32_t vdst = smem_u32(Vsm + row * AST + half);
        #pragma unroll
        for (int i = 0; i < 4; i++) {
            cp16(pdst + i * 16, base + i * 8);
            cp16(kdst + i * 16, base + EMBED + i * 8);
            cp16(vdst + i * 16, base + 2 * EMBED + i * 8);
        }
        cp_commit();
    }
    cp_wait0();
    __syncthreads();

    const uint32_t ks_b = smem_u32(Ksm);
    const uint32_t vs_b = smem_u32(Vsm);
    const uint32_t pb_b = smem_u32(Pbm);
    const uint32_t ROWB = AST * 2;
    const uint32_t pbA = pb_b +
        (((wrow + (lane & 15)) * AST + ((lane >> 4) << 3)) << 1);
    const uint32_t ksB = ks_b +
        ((((((lane >> 4) & 1) << 3) + (lane & 7)) * AST +
          (((lane >> 3) & 1) << 3)) << 1);
    const uint32_t vsB = vs_b +
        ((((((lane >> 3) & 1) << 3) + (lane & 7)) * AST +
          (((lane >> 4) & 1) << 3)) << 1);

    uint32_t aQ[4][4];
    #pragma unroll
    for (int ks = 0; ks < 4; ks++)
        ldsm_x4(aQ[ks], pbA + ks * 32);

    const float SC = 0.125f * 1.4426950408889634f;

    float mx[2] = {-1e30f, -1e30f}, lsum[2] = {0.f, 0.f};
    float Oacc[8][4];
    #pragma unroll
    for (int nt = 0; nt < 8; nt++)
        #pragma unroll
        for (int i = 0; i < 4; i++) Oacc[nt][i] = 0.f;

    for (int c = 0; c < 4; c++) {
        const int n0 = c * 64;

        float Sacc[8][4];
        #pragma unroll
        for (int nt = 0; nt < 8; nt++)
            #pragma unroll
            for (int i = 0; i < 4; i++) Sacc[nt][i] = 0.f;

        #pragma unroll
        for (int ks = 0; ks < 4; ks++) {
            uint32_t bf[16];
            #pragma unroll
            for (int ntp = 0; ntp < 4; ntp++)
                ldsm_x4(&bf[ntp * 4], ksB + (n0 + ntp * 16) * ROWB + ks * 32);
            #pragma unroll
            for (int nt = 0; nt < 8; nt++)
                mma_f16(Sacc[nt], aQ[ks],
                        &bf[((nt >> 1) << 2) + ((nt & 1) << 1)]);
        }

        #pragma unroll
        for (int hf = 0; hf < 2; hf++) {
            float rm = -1e30f;
            #pragma unroll
            for (int nt = 0; nt < 8; nt++) {
                rm = fmaxf(rm, Sacc[nt][2*hf]);
                rm = fmaxf(rm, Sacc[nt][2*hf+1]);
            }
            rm = fmaxf(rm, __shfl_xor_sync(0xffffffffu, rm, 1));
            rm = fmaxf(rm, __shfl_xor_sync(0xffffffffu, rm, 2));
            float nmx = fmaxf(mx[hf], rm * SC);
            float corr = ex2f(mx[hf] - nmx);
            mx[hf] = nmx;

            float ps = 0.f;
            #pragma unroll
            for (int nt = 0; nt < 8; nt++) {
                float p0 = ex2f(fmaf(Sacc[nt][2*hf],   SC, -nmx));
                float p1 = ex2f(fmaf(Sacc[nt][2*hf+1], SC, -nmx));
                ps += p0 + p1;
                Sacc[nt][2*hf]   = p0;
                Sacc[nt][2*hf+1] = p1;
            }
            ps += __shfl_xor_sync(0xffffffffu, ps, 1);
            ps += __shfl_xor_sync(0xffffffffu, ps, 2);
            lsum[hf] = lsum[hf] * corr + ps;

            #pragma unroll
            for (int nt = 0; nt < 8; nt++) {
                Oacc[nt][2*hf]   *= corr;
                Oacc[nt][2*hf+1] *= corr;
            }
        }

        // ---- O += P V chunk: P fragments straight from Sacc registers ----
        #pragma unroll
        for (int ks = 0; ks < 4; ks++) {
            uint32_t aP[4], bv[16];
            aP[0] = packh2(Sacc[2*ks    ][0], Sacc[2*ks    ][1]);
            aP[1] = packh2(Sacc[2*ks    ][2], Sacc[2*ks    ][3]);
            aP[2] = packh2(Sacc[2*ks + 1][0], Sacc[2*ks + 1][1]);
            aP[3] = packh2(Sacc[2*ks + 1][2], Sacc[2*ks + 1][3]);
            #pragma unroll
            for (int ntp = 0; ntp < 4; ntp++)
                ldsm_x4_t(&bv[ntp * 4], vsB + (n0 + ks * 16) * ROWB + ntp * 32);
            #pragma unroll
            for (int nt = 0; nt < 8; nt++)
                mma_f16(Oacc[nt], aP,
                        &bv[((nt >> 1) << 2) + ((nt & 1) << 1)]);
        }
    }

    {
        int r0 = wrow + g4;
        float inv0 = 1.f / lsum[0];
        float inv1 = 1.f / lsum[1];
        int o0 = kvidx[w * WSIZE + r0];
        int o1 = kvidx[w * WSIZE + r0 + 8];
        __half* base0 = &osc[(size_t)o0 * EMBED + h * HDIM];
        __half* base1 = &osc[(size_t)o1 * EMBED + h * HDIM];
        #pragma unroll
        for (int nt = 0; nt < 8; nt++) {
            int col = nt * 8 + 2 * l4;
            *reinterpret_cast<uint32_t*>(base0 + col) =
                packh2(Oacc[nt][0] * inv0, Oacc[nt][1] * inv0);
            *reinterpret_cast<uint32_t*>(base1 + col) =
                packh2(Oacc[nt][2] * inv1, Oacc[nt][3] * inv1);
        }
    }
}

// ---------------------------------------------------------------------------
extern "C" void kernel_launch(void* const* d_in, const int* in_sizes, int n_in,
                              void* d_out, int out_size)
{
    const float* x      = (const float*)d_in[0];
    const float* qkv_w  = (const float*)d_in[1];
    const float* qkv_b  = (const float*)d_in[2];
    const float* proj_w = (const float*)d_in[3];
    const float* proj_b = (const float*)d_in[4];
    const float* rope_c = (const float*)d_in[6];
    const float* rope_s = (const float*)d_in[7];
    const int*   kvi    = (const int*)d_in[8];
    float*       out    = (float*)d_out;

    __half *xh, *wqkv, *wproj, *qkvh, *osch;
    cudaGetSymbolAddress((void**)&xh,    g_xh);
    cudaGetSymbolAddress((void**)&wqkv,  g_wqkv);
    cudaGetSymbolAddress((void**)&wproj, g_wproj);
    cudaGetSymbolAddress((void**)&qkvh,  g_qkvh);
    cudaGetSymbolAddress((void**)&osch,  g_osch);

    // 0) fused fp32 -> fp16 conversions (one launch)
    {
        int nx_src = LTOT * EMBED, nx_tot = MTOT * EMBED;
        int nw = QKVN * EMBED, np = EMBED * EMBED;
        int total = nx_tot + nw + np;
        cvt3_kernel<<<(total / 4 + 255) / 256, 256>>>(
            x, xh, nx_src, nx_tot, qkv_w, wqkv, nw, proj_w, wproj, np);
    }

    cudaFuncSetAttribute(h16_gemm_kernel,
                         cudaFuncAttributeMaxDynamicSharedMemorySize, GEMM_SMEM_B);

    // 1) QKV GEMM, fused gather + bias + ROPE epilogue (fp16 out)
    {
        dim3 grid(QKVN / 128, MTOT / 128);
        h16_gemm_kernel<<<grid, 128, GEMM_SMEM_B>>>(xh, wqkv, qkv_b, nullptr, qkvh,
                                                    kvi, rope_c, rope_s,
                                                    MTOT, QKVN, EMBED);
    }

    // 2) fp16 flash attention (pre-roped q/k; P-in-register; scatter fused)
    {
        cudaFuncSetAttribute(attn_tc_kernel,
                             cudaFuncAttributeMaxDynamicSharedMemorySize, ATTN_SMEM_B);
        dim3 grid(NWIN, NHEADS);
        attn_tc_kernel<<<grid, 512, ATTN_SMEM_B>>>(qkvh, kvi, osch);
    }

    // 3) Output projection (fp16 in, fp32 out, no rope)
    {
        dim3 grid(EMBED / 128, (LTOT + 127) / 128);
        h16_gemm_kernel<<<grid, 128, GEMM_SMEM_B>>>(osch, wproj, proj_b, out, nullptr,
                                                    nullptr, nullptr, nullptr,
                                                    LTOT, EMBED, EMBED);
    }
}